// round 2
// baseline (speedup 1.0000x reference)
#include <cuda_runtime.h>
#include <math.h>

// ---------------- problem constants (fixed shapes) ----------------
#define BCH 4
#define SEQ 2048
#define CH  1024
#define NH  16
#define HD  64
#define LR  20
#define RS  200
#define QKW (2*CH)

// ---------------- scratch (device globals: no allocs allowed) ----------------
__device__ float g_qk[(size_t)BCH * SEQ * QKW];   // 64 MB: qk = x @ qk_w.T
__device__ float g_attn[(size_t)BCH * SEQ * CH];  // 32 MB: mixed scores, [B,N,C]
__device__ float g_web[BCH * NH * HD * LR];
__device__ float g_wrb[BCH * NH * HD * LR];

// ---------------- SGEMM: C[m,n] = sum_k A[m,k]*B[n,k] (+bias[n]) ----------------
// A: row-major MxK (K contiguous), B: row-major NnxK (K contiguous).
// 128x128 block tile, BK=16, 256 threads, 8x8 microtile per thread.
__global__ __launch_bounds__(256) void sgemm_nt(
    const float* __restrict__ A, const float* __restrict__ B,
    const float* __restrict__ bias, float* __restrict__ C,
    int M, int Nn, int K)
{
    const int BK = 16;
    __shared__ float As[BK][128];
    __shared__ float Bs[BK][128];

    const int bm = blockIdx.y * 128;
    const int bn = blockIdx.x * 128;
    const int tid = threadIdx.x;
    const int tm = (tid >> 4) << 3;   // 0..120
    const int tn = (tid & 15) << 3;   // 0..120

    float acc[8][8];
#pragma unroll
    for (int i = 0; i < 8; i++)
#pragma unroll
        for (int j = 0; j < 8; j++) acc[i][j] = 0.f;

    for (int k0 = 0; k0 < K; k0 += BK) {
#pragma unroll
        for (int t = 0; t < 2; t++) {
            int idx = tid + t * 256;          // 0..511
            int row = idx >> 2;               // 0..127
            int c4  = (idx & 3) << 2;         // 0,4,8,12
            float4 va = *(const float4*)(A + (size_t)(bm + row) * K + k0 + c4);
            As[c4 + 0][row] = va.x; As[c4 + 1][row] = va.y;
            As[c4 + 2][row] = va.z; As[c4 + 3][row] = va.w;
            float4 vb = *(const float4*)(B + (size_t)(bn + row) * K + k0 + c4);
            Bs[c4 + 0][row] = vb.x; Bs[c4 + 1][row] = vb.y;
            Bs[c4 + 2][row] = vb.z; Bs[c4 + 3][row] = vb.w;
        }
        __syncthreads();

#pragma unroll
        for (int kk = 0; kk < BK; kk++) {
            float ra[8], rb[8];
#pragma unroll
            for (int i = 0; i < 8; i++) ra[i] = As[kk][tm + i];
#pragma unroll
            for (int j = 0; j < 8; j++) rb[j] = Bs[kk][tn + j];
#pragma unroll
            for (int i = 0; i < 8; i++)
#pragma unroll
                for (int j = 0; j < 8; j++)
                    acc[i][j] += ra[i] * rb[j];
        }
        __syncthreads();
    }

    float bb[8];
#pragma unroll
    for (int j = 0; j < 8; j++) bb[j] = bias ? bias[bn + tn + j] : 0.f;

#pragma unroll
    for (int i = 0; i < 8; i++) {
        float* cp = C + (size_t)(bm + tm + i) * Nn + bn + tn;
        float4 v0, v1;
        v0.x = acc[i][0] + bb[0]; v0.y = acc[i][1] + bb[1];
        v0.z = acc[i][2] + bb[2]; v0.w = acc[i][3] + bb[3];
        v1.x = acc[i][4] + bb[4]; v1.y = acc[i][5] + bb[5];
        v1.z = acc[i][6] + bb[6]; v1.w = acc[i][7] + bb[7];
        *(float4*)(cp)     = v0;
        *(float4*)(cp + 4) = v1;
    }
}

// ---------------- gen_weights: we_b/wr_b [B,H,hd,lr] ----------------
// xh[b,h,d,r] = x[b, idx[r], h*64+d];  we_b[b,h,d,e] = sum_r xh * we[h,r,e]
// One block per (b,h), 64 threads (thread = d).
__global__ __launch_bounds__(64) void genw_kernel(
    const float* __restrict__ x, const float* __restrict__ we,
    const float* __restrict__ wr, float* __restrict__ web,
    float* __restrict__ wrb)
{
    __shared__ float s_we[RS][LR];
    __shared__ float s_wr[RS][LR];
    __shared__ int   s_idx[RS];

    const int b = blockIdx.x >> 4;
    const int h = blockIdx.x & 15;
    const int tid = threadIdx.x;

    for (int i = tid; i < RS * LR; i += 64) {
        ((float*)s_we)[i] = we[h * RS * LR + i];
        ((float*)s_wr)[i] = wr[h * RS * LR + i];
    }
    // np.linspace(0, N-1, R) computed in double, truncated; numpy forces the
    // endpoint to exactly N-1.
    const double step = (double)(SEQ - 1) / (double)(RS - 1);
    for (int r = tid; r < RS; r += 64)
        s_idx[r] = (r == RS - 1) ? (SEQ - 1) : (int)((double)r * step);
    __syncthreads();

    const int d = tid;
    float accE[LR], accR[LR];
#pragma unroll
    for (int e = 0; e < LR; e++) { accE[e] = 0.f; accR[e] = 0.f; }

    for (int r = 0; r < RS; r++) {
        float xv = x[((size_t)b * SEQ + s_idx[r]) * CH + h * HD + d];
#pragma unroll
        for (int e = 0; e < LR; e++) {
            accE[e] += xv * s_we[r][e];
            accR[e] += xv * s_wr[r][e];
        }
    }
    size_t base = ((size_t)(b * NH + h) * HD + d) * LR;
#pragma unroll
    for (int e = 0; e < LR; e++) {
        web[base + e] = accE[e];
        wrb[base + e] = accR[e];
    }
}

// ---------------- normalize + low-rank scores + cw mix ----------------
// Per (b,h,n): q,k = qk rows (normalized over hd); escore = qn @ we_b,
// rscore = kn @ wr_b; attn[d'] = cw_w[d',:] . concat(escore,rscore) + cw_b[d'].
// Write into g_attn[b,n,h*64+d'].
// Block = (b,h, 128-row n tile), 8 warps, warp handles 16 rows.
__global__ __launch_bounds__(256) void score_kernel(
    const float* __restrict__ qk, const float* __restrict__ web,
    const float* __restrict__ wrb, const float* __restrict__ cw_w,
    const float* __restrict__ cw_b, float* __restrict__ attn)
{
    __shared__ float s_web[HD][LR + 1];
    __shared__ float s_wrb[HD][LR + 1];
    __shared__ float s_cw[HD][2 * LR + 1];
    __shared__ float s_cwb[HD];
    __shared__ float s_q[8][HD];
    __shared__ float s_k[8][HD];
    __shared__ float s_sc[8][2 * LR];

    const int tile = blockIdx.x & 15;
    const int h    = (blockIdx.x >> 4) & 15;
    const int b    = blockIdx.x >> 8;
    const int tid = threadIdx.x, w = tid >> 5, lane = tid & 31;

    for (int i = tid; i < HD * LR; i += 256) {
        int d = i / LR, e = i % LR;
        size_t g = ((size_t)(b * NH + h) * HD + d) * LR + e;
        s_web[d][e] = web[g];
        s_wrb[d][e] = wrb[g];
    }
    for (int i = tid; i < HD * 2 * LR; i += 256)
        s_cw[i / (2 * LR)][i % (2 * LR)] = cw_w[i];
    if (tid < HD) s_cwb[tid] = cw_b[tid];
    __syncthreads();

    const int n0 = tile * 128;
    for (int r = 0; r < 16; r++) {
        int n = n0 + r * 8 + w;
        size_t rowoff = ((size_t)b * SEQ + n) * QKW + h * HD;
        float2 qv = *(const float2*)(qk + rowoff + lane * 2);
        float2 kv = *(const float2*)(qk + rowoff + CH + lane * 2);

        float qs = qv.x * qv.x + qv.y * qv.y;
        float ks = kv.x * kv.x + kv.y * kv.y;
#pragma unroll
        for (int o = 16; o > 0; o >>= 1) {
            qs += __shfl_xor_sync(0xffffffffu, qs, o);
            ks += __shfl_xor_sync(0xffffffffu, ks, o);
        }
        float qscale = 1.f / fmaxf(sqrtf(qs), 1e-12f);
        float kscale = 1.f / fmaxf(sqrtf(ks), 1e-12f);
        s_q[w][lane * 2]     = qv.x * qscale;
        s_q[w][lane * 2 + 1] = qv.y * qscale;
        s_k[w][lane * 2]     = kv.x * kscale;
        s_k[w][lane * 2 + 1] = kv.y * kscale;
        __syncwarp();

        // scores j = lane (0..31) and j = 32+lane for lanes 0..7
        float sc0 = 0.f, sc1 = 0.f;
        if (lane < LR) {
#pragma unroll
            for (int d = 0; d < HD; d++) sc0 += s_q[w][d] * s_web[d][lane];
        } else {
#pragma unroll
            for (int d = 0; d < HD; d++) sc0 += s_k[w][d] * s_wrb[d][lane - LR];
        }
        if (lane < 8) {
#pragma unroll
            for (int d = 0; d < HD; d++) sc1 += s_k[w][d] * s_wrb[d][12 + lane];
        }
        s_sc[w][lane] = sc0;
        if (lane < 8) s_sc[w][32 + lane] = sc1;
        __syncwarp();

        float a0 = s_cwb[lane], a1 = s_cwb[lane + 32];
#pragma unroll
        for (int j = 0; j < 2 * LR; j++) {
            float s = s_sc[w][j];
            a0 += s_cw[lane][j] * s;
            a1 += s_cw[lane + 32][j] * s;
        }
        float* outp = attn + ((size_t)b * SEQ + n) * CH + h * HD;
        outp[lane]      = a0;
        outp[lane + 32] = a1;
        __syncwarp();
    }
}

// ---------------- launch ----------------
extern "C" void kernel_launch(void* const* d_in, const int* in_sizes, int n_in,
                              void* d_out, int out_size)
{
    const float* x      = (const float*)d_in[0];
    const float* qk_w   = (const float*)d_in[1];
    const float* proj_w = (const float*)d_in[2];
    const float* proj_b = (const float*)d_in[3];
    const float* we     = (const float*)d_in[4];
    const float* wr     = (const float*)d_in[5];
    const float* cw_w   = (const float*)d_in[6];
    const float* cw_b   = (const float*)d_in[7];
    float* out = (float*)d_out;

    float *qkbuf, *attnbuf, *webbuf, *wrbbuf;
    cudaGetSymbolAddress((void**)&qkbuf,  g_qk);
    cudaGetSymbolAddress((void**)&attnbuf, g_attn);
    cudaGetSymbolAddress((void**)&webbuf, g_web);
    cudaGetSymbolAddress((void**)&wrbbuf, g_wrb);

    // 1) qk = x @ qk_w.T   (M=8192, Nn=2048, K=1024)
    {
        dim3 grid(QKW / 128, (BCH * SEQ) / 128);
        sgemm_nt<<<grid, 256>>>(x, qk_w, nullptr, qkbuf, BCH * SEQ, QKW, CH);
    }
    // 2) we_b / wr_b (tiny)
    genw_kernel<<<BCH * NH, 64>>>(x, we, wr, webbuf, wrbbuf);
    // 3) normalize + scores + cw mix -> g_attn [B,N,C]
    score_kernel<<<BCH * NH * (SEQ / 128), 256>>>(qkbuf, webbuf, wrbbuf,
                                                  cw_w, cw_b, attnbuf);
    // 4) out = attn @ proj_w.T + proj_b   (M=8192, Nn=1024, K=1024)
    {
        dim3 grid(CH / 128, (BCH * SEQ) / 128);
        sgemm_nt<<<grid, 256>>>(attnbuf, proj_w, proj_b, out,
                                BCH * SEQ, CH, CH);
    }
}

// round 4
// speedup vs baseline: 1.8875x; 1.8875x over previous
#include <cuda_runtime.h>
#include <cstdint>
#include <math.h>

// ---------------- problem constants ----------------
#define BCH 4
#define SEQ 2048
#define CH  1024
#define NH  16
#define HD  64
#define LR  20
#define RS  200
#define QKW (2*CH)
#define MTOT (BCH*SEQ)    // 8192
#define BK   32
#define PADK 36           // smem row stride (floats): banks (4m+k)%32 all-distinct
#define NSTAGE (CH/BK)    // 32

// ---------------- scratch (device globals) ----------------
__device__ __align__(256) float g_qk[(size_t)MTOT * QKW];
__device__ __align__(256) float g_attn[(size_t)MTOT * CH];
__device__ __align__(256) float g_web[BCH * NH * HD * LR];
__device__ __align__(256) float g_wrb[BCH * NH * HD * LR];

// ---------------- helpers ----------------
__device__ __forceinline__ float tf32r(float x) {
    float y;
    asm("cvt.rna.tf32.f32 %0, %1;" : "=f"(y) : "f"(x));
    return y;
}
__device__ __forceinline__ void mma8(float* d, const float* a, const float* b) {
    asm volatile(
        "mma.sync.aligned.m16n8k8.row.col.f32.tf32.tf32.f32 "
        "{%0,%1,%2,%3}, {%4,%5,%6,%7}, {%8,%9}, {%0,%1,%2,%3};"
        : "+f"(d[0]), "+f"(d[1]), "+f"(d[2]), "+f"(d[3])
        : "r"(__float_as_uint(a[0])), "r"(__float_as_uint(a[1])),
          "r"(__float_as_uint(a[2])), "r"(__float_as_uint(a[3])),
          "r"(__float_as_uint(b[0])), "r"(__float_as_uint(b[1])));
}

// ---------------- tf32 tensor GEMM: C[m,n] = sum_k A[m,k]*B[n,k] (+bias) ----
// A: [M, 1024] fp32 row-major; B: [Nn, 1024] fp32 row-major; C: [M, Nn] fp32.
// CTA 128x128, 256 thr (2x4 warps, warp tile 64x32), BK=32 double-buffered.
__global__ __launch_bounds__(256) void gemm_tf32(
    const float* __restrict__ A, const float* __restrict__ B,
    const float* __restrict__ bias, float* __restrict__ C, int Nn)
{
    extern __shared__ float sm[];
    float* Abuf[2] = { sm,                sm + 128 * PADK };
    float* Bbuf[2] = { sm + 2*128*PADK,   sm + 3*128*PADK };

    const int tid = threadIdx.x;
    const int wid = tid >> 5, lane = tid & 31;
    const int wm = wid >> 2;          // 0..1 -> m offset 64*wm
    const int wn = wid & 3;           // 0..3 -> n offset 32*wn
    const int gid = lane >> 2;        // groupID 0..7
    const int tig = lane & 3;         // threadID_in_group 0..3
    const int m0 = blockIdx.y * 128, n0 = blockIdx.x * 128;

    // copy indices: 4 segments each for A and B per stage
    int crow[4], cks[4];
#pragma unroll
    for (int i = 0; i < 4; i++) {
        int s = tid + 256 * i;        // 0..1023
        crow[i] = s >> 3;             // 0..127
        cks[i]  = (s & 7) * 4;        // 0..28
    }

    float acc[4][4][4];
#pragma unroll
    for (int mt = 0; mt < 4; mt++)
#pragma unroll
        for (int nt = 0; nt < 4; nt++)
#pragma unroll
            for (int r = 0; r < 4; r++) acc[mt][nt][r] = 0.f;

    // ---- stage 0 load ----
#pragma unroll
    for (int i = 0; i < 4; i++) {
        float4 va = *(const float4*)(A + (size_t)(m0 + crow[i]) * CH + cks[i]);
        float* p = Abuf[0] + crow[i] * PADK + cks[i];
        p[0] = tf32r(va.x); p[1] = tf32r(va.y); p[2] = tf32r(va.z); p[3] = tf32r(va.w);
        float4 vb = *(const float4*)(B + (size_t)(n0 + crow[i]) * CH + cks[i]);
        float* q = Bbuf[0] + crow[i] * PADK + cks[i];
        q[0] = tf32r(vb.x); q[1] = tf32r(vb.y); q[2] = tf32r(vb.z); q[3] = tf32r(vb.w);
    }
    __syncthreads();

    for (int c = 0; c < NSTAGE; c++) {
        const int buf = c & 1;
        float4 pa[4], pb[4];
        if (c + 1 < NSTAGE) {
            const int k0 = (c + 1) * BK;
#pragma unroll
            for (int i = 0; i < 4; i++) {
                pa[i] = *(const float4*)(A + (size_t)(m0 + crow[i]) * CH + k0 + cks[i]);
                pb[i] = *(const float4*)(B + (size_t)(n0 + crow[i]) * CH + k0 + cks[i]);
            }
        }

        const float* As = Abuf[buf];
        const float* Bs = Bbuf[buf];
#pragma unroll
        for (int ks = 0; ks < BK; ks += 8) {
            float af[4][4], bf[4][2];
#pragma unroll
            for (int mt = 0; mt < 4; mt++) {
                int m = wm * 64 + mt * 16 + gid;
                af[mt][0] = As[m * PADK + ks + tig];
                af[mt][1] = As[(m + 8) * PADK + ks + tig];
                af[mt][2] = As[m * PADK + ks + 4 + tig];
                af[mt][3] = As[(m + 8) * PADK + ks + 4 + tig];
            }
#pragma unroll
            for (int nt = 0; nt < 4; nt++) {
                int n = wn * 32 + nt * 8 + gid;
                bf[nt][0] = Bs[n * PADK + ks + tig];
                bf[nt][1] = Bs[n * PADK + ks + 4 + tig];
            }
#pragma unroll
            for (int mt = 0; mt < 4; mt++)
#pragma unroll
                for (int nt = 0; nt < 4; nt++)
                    mma8(acc[mt][nt], af[mt], bf[nt]);
        }

        if (c + 1 < NSTAGE) {
            float* pA = Abuf[buf ^ 1];
            float* pB = Bbuf[buf ^ 1];
#pragma unroll
            for (int i = 0; i < 4; i++) {
                float* p = pA + crow[i] * PADK + cks[i];
                p[0] = tf32r(pa[i].x); p[1] = tf32r(pa[i].y);
                p[2] = tf32r(pa[i].z); p[3] = tf32r(pa[i].w);
                float* q = pB + crow[i] * PADK + cks[i];
                q[0] = tf32r(pb[i].x); q[1] = tf32r(pb[i].y);
                q[2] = tf32r(pb[i].z); q[3] = tf32r(pb[i].w);
            }
        }
        __syncthreads();
    }

    // ---- epilogue ----
    float bb[4][2];
#pragma unroll
    for (int nt = 0; nt < 4; nt++) {
        int col = n0 + wn * 32 + nt * 8 + tig * 2;
        bb[nt][0] = bias ? bias[col]     : 0.f;
        bb[nt][1] = bias ? bias[col + 1] : 0.f;
    }
#pragma unroll
    for (int mt = 0; mt < 4; mt++) {
#pragma unroll
        for (int half = 0; half < 2; half++) {
            int row = m0 + wm * 64 + mt * 16 + gid + half * 8;
            float* cp = C + (size_t)row * Nn + n0 + wn * 32 + tig * 2;
#pragma unroll
            for (int nt = 0; nt < 4; nt++) {
                float2 v;
                v.x = acc[mt][nt][half * 2 + 0] + bb[nt][0];
                v.y = acc[mt][nt][half * 2 + 1] + bb[nt][1];
                *(float2*)(cp + nt * 8) = v;
            }
        }
    }
}

// ---------------- gen_weights (unchanged) ----------------
__global__ __launch_bounds__(64) void genw_kernel(
    const float* __restrict__ x, const float* __restrict__ we,
    const float* __restrict__ wr, float* __restrict__ web,
    float* __restrict__ wrb)
{
    __shared__ float s_we[RS][LR];
    __shared__ float s_wr[RS][LR];
    __shared__ int   s_idx[RS];

    const int b = blockIdx.x >> 4;
    const int h = blockIdx.x & 15;
    const int tid = threadIdx.x;

    for (int i = tid; i < RS * LR; i += 64) {
        ((float*)s_we)[i] = we[h * RS * LR + i];
        ((float*)s_wr)[i] = wr[h * RS * LR + i];
    }
    const double step = (double)(SEQ - 1) / (double)(RS - 1);
    for (int r = tid; r < RS; r += 64)
        s_idx[r] = (r == RS - 1) ? (SEQ - 1) : (int)((double)r * step);
    __syncthreads();

    const int d = tid;
    float accE[LR], accR[LR];
#pragma unroll
    for (int e = 0; e < LR; e++) { accE[e] = 0.f; accR[e] = 0.f; }

    for (int r = 0; r < RS; r++) {
        float xv = x[((size_t)b * SEQ + s_idx[r]) * CH + h * HD + d];
#pragma unroll
        for (int e = 0; e < LR; e++) {
            accE[e] += xv * s_we[r][e];
            accR[e] += xv * s_wr[r][e];
        }
    }
    size_t base = ((size_t)(b * NH + h) * HD + d) * LR;
#pragma unroll
    for (int e = 0; e < LR; e++) {
        web[base + e] = accE[e];
        wrb[base + e] = accR[e];
    }
}

// ---------------- score kernel (same math, 4x more blocks) ----------------
__global__ __launch_bounds__(256) void score_kernel(
    const float* __restrict__ qk, const float* __restrict__ web,
    const float* __restrict__ wrb, const float* __restrict__ cw_w,
    const float* __restrict__ cw_b, float* __restrict__ attn)
{
    __shared__ float s_web[HD][LR + 1];
    __shared__ float s_wrb[HD][LR + 1];
    __shared__ float s_cw[HD][2 * LR + 1];
    __shared__ float s_cwb[HD];
    __shared__ float s_q[8][HD];
    __shared__ float s_k[8][HD];
    __shared__ float s_sc[8][2 * LR];

    const int tile = blockIdx.x & 63;          // 64 tiles of 32 rows
    const int h    = (blockIdx.x >> 6) & 15;
    const int b    = blockIdx.x >> 10;
    const int tid = threadIdx.x, w = tid >> 5, lane = tid & 31;

    for (int i = tid; i < HD * LR; i += 256) {
        int d = i / LR, e = i % LR;
        size_t g = ((size_t)(b * NH + h) * HD + d) * LR + e;
        s_web[d][e] = web[g];
        s_wrb[d][e] = wrb[g];
    }
    for (int i = tid; i < HD * 2 * LR; i += 256)
        s_cw[i / (2 * LR)][i % (2 * LR)] = cw_w[i];
    if (tid < HD) s_cwb[tid] = cw_b[tid];
    __syncthreads();

    const int n0 = tile * 32;
    for (int r = 0; r < 4; r++) {
        int n = n0 + r * 8 + w;
        size_t rowoff = ((size_t)b * SEQ + n) * QKW + h * HD;
        float2 qv = *(const float2*)(qk + rowoff + lane * 2);
        float2 kv = *(const float2*)(qk + rowoff + CH + lane * 2);

        float qs = qv.x * qv.x + qv.y * qv.y;
        float ks = kv.x * kv.x + kv.y * kv.y;
#pragma unroll
        for (int o = 16; o > 0; o >>= 1) {
            qs += __shfl_xor_sync(0xffffffffu, qs, o);
            ks += __shfl_xor_sync(0xffffffffu, ks, o);
        }
        float qscale = 1.f / fmaxf(sqrtf(qs), 1e-12f);
        float kscale = 1.f / fmaxf(sqrtf(ks), 1e-12f);
        s_q[w][lane * 2]     = qv.x * qscale;
        s_q[w][lane * 2 + 1] = qv.y * qscale;
        s_k[w][lane * 2]     = kv.x * kscale;
        s_k[w][lane * 2 + 1] = kv.y * kscale;
        __syncwarp();

        float sc0 = 0.f, sc1 = 0.f;
        if (lane < LR) {
#pragma unroll
            for (int d = 0; d < HD; d++) sc0 += s_q[w][d] * s_web[d][lane];
        } else {
#pragma unroll
            for (int d = 0; d < HD; d++) sc0 += s_k[w][d] * s_wrb[d][lane - LR];
        }
        if (lane < 8) {
#pragma unroll
            for (int d = 0; d < HD; d++) sc1 += s_k[w][d] * s_wrb[d][12 + lane];
        }
        s_sc[w][lane] = sc0;
        if (lane < 8) s_sc[w][32 + lane] = sc1;
        __syncwarp();

        float a0 = s_cwb[lane], a1 = s_cwb[lane + 32];
#pragma unroll
        for (int j = 0; j < 2 * LR; j++) {
            float s = s_sc[w][j];
            a0 += s_cw[lane][j] * s;
            a1 += s_cw[lane + 32][j] * s;
        }
        float* outp = attn + ((size_t)b * SEQ + n) * CH + h * HD;
        outp[lane]      = a0;
        outp[lane + 32] = a1;
        __syncwarp();
    }
}

// ---------------- launch ----------------
extern "C" void kernel_launch(void* const* d_in, const int* in_sizes, int n_in,
                              void* d_out, int out_size)
{
    const float* x      = (const float*)d_in[0];
    const float* qk_w   = (const float*)d_in[1];
    const float* proj_w = (const float*)d_in[2];
    const float* proj_b = (const float*)d_in[3];
    const float* we     = (const float*)d_in[4];
    const float* wr     = (const float*)d_in[5];
    const float* cw_w   = (const float*)d_in[6];
    const float* cw_b   = (const float*)d_in[7];
    float* out = (float*)d_out;

    float *qkbuf, *attnbuf, *webbuf, *wrbbuf;
    cudaGetSymbolAddress((void**)&qkbuf,  g_qk);
    cudaGetSymbolAddress((void**)&attnbuf, g_attn);
    cudaGetSymbolAddress((void**)&webbuf, g_web);
    cudaGetSymbolAddress((void**)&wrbbuf, g_wrb);

    const int smem_bytes = 4 * 128 * PADK * 4;   // 73728
    cudaFuncSetAttribute(gemm_tf32,
                         cudaFuncAttributeMaxDynamicSharedMemorySize, smem_bytes);

    // 1) qk = x @ qk_w.T   (M=8192, Nn=2048)
    {
        dim3 grid(QKW / 128, MTOT / 128);
        gemm_tf32<<<grid, 256, smem_bytes>>>(x, qk_w, nullptr, qkbuf, QKW);
    }
    // 2) we_b / wr_b (tiny)
    genw_kernel<<<BCH * NH, 64>>>(x, we, wr, webbuf, wrbbuf);
    // 3) normalize + scores + cw mix -> g_attn
    score_kernel<<<BCH * NH * (SEQ / 32), 256>>>(qkbuf, webbuf, wrbbuf,
                                                 cw_w, cw_b, attnbuf);
    // 4) out = attn @ proj_w.T + proj_b   (M=8192, Nn=1024)
    {
        dim3 grid(CH / 128, MTOT / 128);
        gemm_tf32<<<grid, 256, smem_bytes>>>(attnbuf, proj_w, proj_b, out, CH);
    }
}

// round 5
// speedup vs baseline: 2.3653x; 1.2531x over previous
#include <cuda_runtime.h>
#include <cstdint>
#include <math.h>

// ---------------- problem constants ----------------
#define BCH 4
#define SEQ 2048
#define CH  1024
#define NH  16
#define HD  64
#define LR  20
#define RS  200
#define QKW (2*CH)
#define MTOT (BCH*SEQ)    // 8192
#define BK   32
#define PADK 36           // smem row stride (floats): conflict-free fragments
#define NSTAGE (CH/BK)    // 32
#define STAGE_FLT (2*128*PADK)   // floats per pipeline stage (A+B)

// ---------------- scratch (device globals) ----------------
__device__ __align__(256) float g_qk[(size_t)MTOT * QKW];
__device__ __align__(256) float g_attn[(size_t)MTOT * CH];
__device__ __align__(256) float g_web[BCH * NH * HD * LR];
__device__ __align__(256) float g_wrb[BCH * NH * HD * LR];
__device__ __align__(256) float g_xr[(size_t)MTOT * CH];    // tf32-rounded x
__device__ __align__(256) float g_qkwr[(size_t)QKW * CH];   // tf32-rounded qk_w
__device__ __align__(256) float g_pwr[(size_t)CH * CH];     // tf32-rounded proj_w

// ---------------- helpers ----------------
__device__ __forceinline__ float tf32r(float x) {
    float y;
    asm("cvt.rna.tf32.f32 %0, %1;" : "=f"(y) : "f"(x));
    return y;
}
__device__ __forceinline__ uint32_t smem_u32(const void* p) {
    uint32_t a;
    asm("{ .reg .u64 t; cvta.to.shared.u64 t, %1; cvt.u32.u64 %0, t; }"
        : "=r"(a) : "l"(p));
    return a;
}
#define CP_ASYNC16(dst, src) \
    asm volatile("cp.async.cg.shared.global [%0], [%1], 16;" :: "r"(dst), "l"(src))
#define CP_COMMIT() asm volatile("cp.async.commit_group;" ::: "memory")
#define CP_WAIT2()  asm volatile("cp.async.wait_group 2;" ::: "memory")

__device__ __forceinline__ void mma8(float* d, const float* a, const float* b) {
    asm volatile(
        "mma.sync.aligned.m16n8k8.row.col.f32.tf32.tf32.f32 "
        "{%0,%1,%2,%3}, {%4,%5,%6,%7}, {%8,%9}, {%0,%1,%2,%3};"
        : "+f"(d[0]), "+f"(d[1]), "+f"(d[2]), "+f"(d[3])
        : "r"(__float_as_uint(a[0])), "r"(__float_as_uint(a[1])),
          "r"(__float_as_uint(a[2])), "r"(__float_as_uint(a[3])),
          "r"(__float_as_uint(b[0])), "r"(__float_as_uint(b[1])));
}

// ---------------- tf32 rounding pass ----------------
__global__ __launch_bounds__(256) void round_tf32(
    const float* __restrict__ src, float* __restrict__ dst, int n4)
{
    int i = blockIdx.x * 256 + threadIdx.x;
    if (i >= n4) return;
    float4 v = ((const float4*)src)[i];
    v.x = tf32r(v.x); v.y = tf32r(v.y); v.z = tf32r(v.z); v.w = tf32r(v.w);
    ((float4*)dst)[i] = v;
}

// ---------------- tf32 tensor GEMM (operands pre-rounded) ----------------
// C[m,n] = sum_k A[m,k]*B[n,k] (+bias[n]).  A:[M,1024], B:[Nn,1024], fp32.
// CTA 128x128, 256 thr (2x4 warps, warp tile 64x32), BK=32, 3-stage cp.async.
__global__ __launch_bounds__(256) void gemm_tf32(
    const float* __restrict__ A, const float* __restrict__ B,
    const float* __restrict__ bias, float* __restrict__ C, int Nn)
{
    extern __shared__ float sm[];
    const uint32_t sbase = smem_u32(sm);

    const int tid = threadIdx.x;
    const int wid = tid >> 5, lane = tid & 31;
    const int wm = wid >> 2;          // 0..1 -> m offset 64*wm
    const int wn = wid & 3;           // 0..3 -> n offset 32*wn
    const int gid = lane >> 2;        // 0..7
    const int tig = lane & 3;         // 0..3
    const int m0 = blockIdx.y * 128, n0 = blockIdx.x * 128;

    // per-stage copy: 2048 x 16B chunks, 8 per thread
#define COPY_STAGE(s) do {                                                     \
        const int _k0 = (s) * BK;                                              \
        const uint32_t _db = sbase + ((s) % 3) * (STAGE_FLT * 4);              \
        _Pragma("unroll")                                                      \
        for (int _i = 0; _i < 8; _i++) {                                       \
            int _id  = _i * 256 + tid;                                         \
            int _mat = _id >> 10;                                              \
            int _row = (_id >> 3) & 127;                                       \
            int _c4  = (_id & 7) * 4;                                          \
            const float* _src = (_mat ? (B + (size_t)(n0 + _row) * CH)         \
                                      : (A + (size_t)(m0 + _row) * CH))        \
                                + _k0 + _c4;                                   \
            uint32_t _dst = _db + (uint32_t)(_mat * 128 * PADK +               \
                                             _row * PADK + _c4) * 4u;          \
            CP_ASYNC16(_dst, _src);                                            \
        }                                                                      \
    } while (0)

    // prime 3 stages
    COPY_STAGE(0); CP_COMMIT();
    COPY_STAGE(1); CP_COMMIT();
    COPY_STAGE(2); CP_COMMIT();

    float acc[4][4][4];
#pragma unroll
    for (int mt = 0; mt < 4; mt++)
#pragma unroll
        for (int nt = 0; nt < 4; nt++)
#pragma unroll
            for (int r = 0; r < 4; r++) acc[mt][nt][r] = 0.f;

    for (int c = 0; c < NSTAGE; c++) {
        CP_WAIT2();
        __syncthreads();
        const float* As = sm + (c % 3) * STAGE_FLT;
        const float* Bs = As + 128 * PADK;

#pragma unroll
        for (int ks = 0; ks < BK; ks += 8) {
            float af[4][4], bf[4][2];
#pragma unroll
            for (int mt = 0; mt < 4; mt++) {
                int m = wm * 64 + mt * 16 + gid;
                af[mt][0] = As[m * PADK + ks + tig];
                af[mt][1] = As[(m + 8) * PADK + ks + tig];
                af[mt][2] = As[m * PADK + ks + 4 + tig];
                af[mt][3] = As[(m + 8) * PADK + ks + 4 + tig];
            }
#pragma unroll
            for (int nt = 0; nt < 4; nt++) {
                int n = wn * 32 + nt * 8 + gid;
                bf[nt][0] = Bs[n * PADK + ks + tig];
                bf[nt][1] = Bs[n * PADK + ks + 4 + tig];
            }
#pragma unroll
            for (int mt = 0; mt < 4; mt++)
#pragma unroll
                for (int nt = 0; nt < 4; nt++)
                    mma8(acc[mt][nt], af[mt], bf[nt]);
        }

        __syncthreads();
        if (c + 3 < NSTAGE) COPY_STAGE(c + 3);
        CP_COMMIT();
    }

    // ---- epilogue ----
    float bb[4][2];
#pragma unroll
    for (int nt = 0; nt < 4; nt++) {
        int col = n0 + wn * 32 + nt * 8 + tig * 2;
        bb[nt][0] = bias ? bias[col]     : 0.f;
        bb[nt][1] = bias ? bias[col + 1] : 0.f;
    }
#pragma unroll
    for (int mt = 0; mt < 4; mt++) {
#pragma unroll
        for (int half = 0; half < 2; half++) {
            int row = m0 + wm * 64 + mt * 16 + gid + half * 8;
            float* cp = C + (size_t)row * Nn + n0 + wn * 32 + tig * 2;
#pragma unroll
            for (int nt = 0; nt < 4; nt++) {
                float2 v;
                v.x = acc[mt][nt][half * 2 + 0] + bb[nt][0];
                v.y = acc[mt][nt][half * 2 + 1] + bb[nt][1];
                *(float2*)(cp + nt * 8) = v;
            }
        }
    }
#undef COPY_STAGE
}

// ---------------- gen_weights (unchanged, verified) ----------------
__global__ __launch_bounds__(64) void genw_kernel(
    const float* __restrict__ x, const float* __restrict__ we,
    const float* __restrict__ wr, float* __restrict__ web,
    float* __restrict__ wrb)
{
    __shared__ float s_we[RS][LR];
    __shared__ float s_wr[RS][LR];
    __shared__ int   s_idx[RS];

    const int b = blockIdx.x >> 4;
    const int h = blockIdx.x & 15;
    const int tid = threadIdx.x;

    for (int i = tid; i < RS * LR; i += 64) {
        ((float*)s_we)[i] = we[h * RS * LR + i];
        ((float*)s_wr)[i] = wr[h * RS * LR + i];
    }
    const double step = (double)(SEQ - 1) / (double)(RS - 1);
    for (int r = tid; r < RS; r += 64)
        s_idx[r] = (r == RS - 1) ? (SEQ - 1) : (int)((double)r * step);
    __syncthreads();

    const int d = tid;
    float accE[LR], accR[LR];
#pragma unroll
    for (int e = 0; e < LR; e++) { accE[e] = 0.f; accR[e] = 0.f; }

    for (int r = 0; r < RS; r++) {
        float xv = x[((size_t)b * SEQ + s_idx[r]) * CH + h * HD + d];
#pragma unroll
        for (int e = 0; e < LR; e++) {
            accE[e] += xv * s_we[r][e];
            accR[e] += xv * s_wr[r][e];
        }
    }
    size_t base = ((size_t)(b * NH + h) * HD + d) * LR;
#pragma unroll
    for (int e = 0; e < LR; e++) {
        web[base + e] = accE[e];
        wrb[base + e] = accR[e];
    }
}

// ---------------- score kernel (writes tf32-rounded attn) ----------------
__global__ __launch_bounds__(256) void score_kernel(
    const float* __restrict__ qk, const float* __restrict__ web,
    const float* __restrict__ wrb, const float* __restrict__ cw_w,
    const float* __restrict__ cw_b, float* __restrict__ attn)
{
    __shared__ float s_web[HD][LR + 1];
    __shared__ float s_wrb[HD][LR + 1];
    __shared__ float s_cw[HD][2 * LR + 1];
    __shared__ float s_cwb[HD];
    __shared__ float s_q[8][HD];
    __shared__ float s_k[8][HD];
    __shared__ float s_sc[8][2 * LR];

    const int tile = blockIdx.x & 63;
    const int h    = (blockIdx.x >> 6) & 15;
    const int b    = blockIdx.x >> 10;
    const int tid = threadIdx.x, w = tid >> 5, lane = tid & 31;

    for (int i = tid; i < HD * LR; i += 256) {
        int d = i / LR, e = i % LR;
        size_t g = ((size_t)(b * NH + h) * HD + d) * LR + e;
        s_web[d][e] = web[g];
        s_wrb[d][e] = wrb[g];
    }
    for (int i = tid; i < HD * 2 * LR; i += 256)
        s_cw[i / (2 * LR)][i % (2 * LR)] = cw_w[i];
    if (tid < HD) s_cwb[tid] = cw_b[tid];
    __syncthreads();

    const int n0 = tile * 32;
    for (int r = 0; r < 4; r++) {
        int n = n0 + r * 8 + w;
        size_t rowoff = ((size_t)b * SEQ + n) * QKW + h * HD;
        float2 qv = *(const float2*)(qk + rowoff + lane * 2);
        float2 kv = *(const float2*)(qk + rowoff + CH + lane * 2);

        float qs = qv.x * qv.x + qv.y * qv.y;
        float ks = kv.x * kv.x + kv.y * kv.y;
#pragma unroll
        for (int o = 16; o > 0; o >>= 1) {
            qs += __shfl_xor_sync(0xffffffffu, qs, o);
            ks += __shfl_xor_sync(0xffffffffu, ks, o);
        }
        float qscale = 1.f / fmaxf(sqrtf(qs), 1e-12f);
        float kscale = 1.f / fmaxf(sqrtf(ks), 1e-12f);
        s_q[w][lane * 2]     = qv.x * qscale;
        s_q[w][lane * 2 + 1] = qv.y * qscale;
        s_k[w][lane * 2]     = kv.x * kscale;
        s_k[w][lane * 2 + 1] = kv.y * kscale;
        __syncwarp();

        float sc0 = 0.f, sc1 = 0.f;
        if (lane < LR) {
#pragma unroll
            for (int d = 0; d < HD; d++) sc0 += s_q[w][d] * s_web[d][lane];
        } else {
#pragma unroll
            for (int d = 0; d < HD; d++) sc0 += s_k[w][d] * s_wrb[d][lane - LR];
        }
        if (lane < 8) {
#pragma unroll
            for (int d = 0; d < HD; d++) sc1 += s_k[w][d] * s_wrb[d][12 + lane];
        }
        s_sc[w][lane] = sc0;
        if (lane < 8) s_sc[w][32 + lane] = sc1;
        __syncwarp();

        float a0 = s_cwb[lane], a1 = s_cwb[lane + 32];
#pragma unroll
        for (int j = 0; j < 2 * LR; j++) {
            float s = s_sc[w][j];
            a0 += s_cw[lane][j] * s;
            a1 += s_cw[lane + 32][j] * s;
        }
        float* outp = attn + ((size_t)b * SEQ + n) * CH + h * HD;
        outp[lane]      = tf32r(a0);   // pre-rounded for GEMM2
        outp[lane + 32] = tf32r(a1);
        __syncwarp();
    }
}

// ---------------- launch ----------------
extern "C" void kernel_launch(void* const* d_in, const int* in_sizes, int n_in,
                              void* d_out, int out_size)
{
    const float* x      = (const float*)d_in[0];
    const float* qk_w   = (const float*)d_in[1];
    const float* proj_w = (const float*)d_in[2];
    const float* proj_b = (const float*)d_in[3];
    const float* we     = (const float*)d_in[4];
    const float* wr     = (const float*)d_in[5];
    const float* cw_w   = (const float*)d_in[6];
    const float* cw_b   = (const float*)d_in[7];
    float* out = (float*)d_out;

    float *qkbuf, *attnbuf, *webbuf, *wrbbuf, *xr, *qkwr, *pwr;
    cudaGetSymbolAddress((void**)&qkbuf,  g_qk);
    cudaGetSymbolAddress((void**)&attnbuf, g_attn);
    cudaGetSymbolAddress((void**)&webbuf, g_web);
    cudaGetSymbolAddress((void**)&wrbbuf, g_wrb);
    cudaGetSymbolAddress((void**)&xr,   g_xr);
    cudaGetSymbolAddress((void**)&qkwr, g_qkwr);
    cudaGetSymbolAddress((void**)&pwr,  g_pwr);

    const int smem_bytes = 3 * STAGE_FLT * 4;   // 110592
    cudaFuncSetAttribute(gemm_tf32,
                         cudaFuncAttributeMaxDynamicSharedMemorySize, smem_bytes);

    // pre-round operands to tf32 grid (one memory pass each)
    round_tf32<<<(MTOT * CH / 4) / 256, 256>>>(x, xr, MTOT * CH / 4);
    round_tf32<<<(QKW * CH / 4) / 256, 256>>>(qk_w, qkwr, QKW * CH / 4);
    round_tf32<<<(CH * CH / 4) / 256, 256>>>(proj_w, pwr, CH * CH / 4);

    // 1) qk = x @ qk_w.T   (M=8192, Nn=2048)
    {
        dim3 grid(QKW / 128, MTOT / 128);
        gemm_tf32<<<grid, 256, smem_bytes>>>(xr, qkwr, nullptr, qkbuf, QKW);
    }
    // 2) we_b / wr_b (tiny; uses original fp32 x)
    genw_kernel<<<BCH * NH, 64>>>(x, we, wr, webbuf, wrbbuf);
    // 3) normalize + scores + cw mix -> rounded attn
    score_kernel<<<BCH * NH * (SEQ / 32), 256>>>(qkbuf, webbuf, wrbbuf,
                                                 cw_w, cw_b, attnbuf);
    // 4) out = attn @ proj_w.T + proj_b   (M=8192, Nn=1024)
    {
        dim3 grid(CH / 128, MTOT / 128);
        gemm_tf32<<<grid, 256, smem_bytes>>>(attnbuf, pwr, proj_b, out, CH);
    }
}

// round 6
// speedup vs baseline: 2.9894x; 1.2639x over previous
#include <cuda_runtime.h>
#include <cstdint>
#include <math.h>

// ---------------- problem constants ----------------
#define BCH 4
#define SEQ 2048
#define CH  1024
#define NH  16
#define HD  64
#define LR  20
#define RS  200
#define QKW (2*CH)
#define MTOT (BCH*SEQ)    // 8192
#define BK   32
#define PADK 36
#define NSTAGE (CH/BK)    // 32
#define STAGE_FLT (2*128*PADK)
#define NBH (BCH*NH)      // 64

// ---------------- scratch (device globals) ----------------
__device__ __align__(256) float g_qk[(size_t)MTOT * QKW];
__device__ __align__(256) float g_attn[(size_t)MTOT * CH];
__device__ __align__(256) float g_xr[(size_t)MTOT * CH];
__device__ __align__(256) float g_qkwr[(size_t)QKW * CH];
__device__ __align__(256) float g_pwr[(size_t)CH * CH];
__device__ __align__(256) float g_qkn[(size_t)NBH * 128 * SEQ];  // [bh][k][n]
__device__ __align__(256) float g_M[(size_t)NBH * 128 * HD];     // [bh][k][dp]

// ---------------- helpers ----------------
__device__ __forceinline__ float tf32r(float x) {
    float y;
    asm("cvt.rna.tf32.f32 %0, %1;" : "=f"(y) : "f"(x));
    return y;
}
__device__ __forceinline__ uint32_t smem_u32(const void* p) {
    uint32_t a;
    asm("{ .reg .u64 t; cvta.to.shared.u64 t, %1; cvt.u32.u64 %0, t; }"
        : "=r"(a) : "l"(p));
    return a;
}
#define CP_ASYNC16(dst, src) \
    asm volatile("cp.async.cg.shared.global [%0], [%1], 16;" :: "r"(dst), "l"(src))
#define CP_COMMIT() asm volatile("cp.async.commit_group;" ::: "memory")
#define CP_WAIT2()  asm volatile("cp.async.wait_group 2;" ::: "memory")

__device__ __forceinline__ void mma8(float* d, const float* a, const float* b) {
    asm volatile(
        "mma.sync.aligned.m16n8k8.row.col.f32.tf32.tf32.f32 "
        "{%0,%1,%2,%3}, {%4,%5,%6,%7}, {%8,%9}, {%0,%1,%2,%3};"
        : "+f"(d[0]), "+f"(d[1]), "+f"(d[2]), "+f"(d[3])
        : "r"(__float_as_uint(a[0])), "r"(__float_as_uint(a[1])),
          "r"(__float_as_uint(a[2])), "r"(__float_as_uint(a[3])),
          "r"(__float_as_uint(b[0])), "r"(__float_as_uint(b[1])));
}

// ---------------- tf32 rounding pass ----------------
__global__ __launch_bounds__(256) void round_tf32(
    const float* __restrict__ src, float* __restrict__ dst, int n4)
{
    int i = blockIdx.x * 256 + threadIdx.x;
    if (i >= n4) return;
    float4 v = ((const float4*)src)[i];
    v.x = tf32r(v.x); v.y = tf32r(v.y); v.z = tf32r(v.z); v.w = tf32r(v.w);
    ((float4*)dst)[i] = v;
}

// ---------------- tf32 tensor GEMM (unchanged from R5) ----------------
__global__ __launch_bounds__(256) void gemm_tf32(
    const float* __restrict__ A, const float* __restrict__ B,
    const float* __restrict__ bias, float* __restrict__ C, int Nn)
{
    extern __shared__ float sm[];
    const uint32_t sbase = smem_u32(sm);

    const int tid = threadIdx.x;
    const int wid = tid >> 5, lane = tid & 31;
    const int wm = wid >> 2;
    const int wn = wid & 3;
    const int gid = lane >> 2;
    const int tig = lane & 3;
    const int m0 = blockIdx.y * 128, n0 = blockIdx.x * 128;

#define COPY_STAGE(s) do {                                                     \
        const int _k0 = (s) * BK;                                              \
        const uint32_t _db = sbase + ((s) % 3) * (STAGE_FLT * 4);              \
        _Pragma("unroll")                                                      \
        for (int _i = 0; _i < 8; _i++) {                                       \
            int _id  = _i * 256 + tid;                                         \
            int _mat = _id >> 10;                                              \
            int _row = (_id >> 3) & 127;                                       \
            int _c4  = (_id & 7) * 4;                                          \
            const float* _src = (_mat ? (B + (size_t)(n0 + _row) * CH)         \
                                      : (A + (size_t)(m0 + _row) * CH))        \
                                + _k0 + _c4;                                   \
            uint32_t _dst = _db + (uint32_t)(_mat * 128 * PADK +               \
                                             _row * PADK + _c4) * 4u;          \
            CP_ASYNC16(_dst, _src);                                            \
        }                                                                      \
    } while (0)

    COPY_STAGE(0); CP_COMMIT();
    COPY_STAGE(1); CP_COMMIT();
    COPY_STAGE(2); CP_COMMIT();

    float acc[4][4][4];
#pragma unroll
    for (int mt = 0; mt < 4; mt++)
#pragma unroll
        for (int nt = 0; nt < 4; nt++)
#pragma unroll
            for (int r = 0; r < 4; r++) acc[mt][nt][r] = 0.f;

    for (int c = 0; c < NSTAGE; c++) {
        CP_WAIT2();
        __syncthreads();
        const float* As = sm + (c % 3) * STAGE_FLT;
        const float* Bs = As + 128 * PADK;

#pragma unroll
        for (int ks = 0; ks < BK; ks += 8) {
            float af[4][4], bf[4][2];
#pragma unroll
            for (int mt = 0; mt < 4; mt++) {
                int m = wm * 64 + mt * 16 + gid;
                af[mt][0] = As[m * PADK + ks + tig];
                af[mt][1] = As[(m + 8) * PADK + ks + tig];
                af[mt][2] = As[m * PADK + ks + 4 + tig];
                af[mt][3] = As[(m + 8) * PADK + ks + 4 + tig];
            }
#pragma unroll
            for (int nt = 0; nt < 4; nt++) {
                int n = wn * 32 + nt * 8 + gid;
                bf[nt][0] = Bs[n * PADK + ks + tig];
                bf[nt][1] = Bs[n * PADK + ks + 4 + tig];
            }
#pragma unroll
            for (int mt = 0; mt < 4; mt++)
#pragma unroll
                for (int nt = 0; nt < 4; nt++)
                    mma8(acc[mt][nt], af[mt], bf[nt]);
        }

        __syncthreads();
        if (c + 3 < NSTAGE) COPY_STAGE(c + 3);
        CP_COMMIT();
    }

    float bb[4][2];
#pragma unroll
    for (int nt = 0; nt < 4; nt++) {
        int col = n0 + wn * 32 + nt * 8 + tig * 2;
        bb[nt][0] = bias ? bias[col]     : 0.f;
        bb[nt][1] = bias ? bias[col + 1] : 0.f;
    }
#pragma unroll
    for (int mt = 0; mt < 4; mt++) {
#pragma unroll
        for (int half = 0; half < 2; half++) {
            int row = m0 + wm * 64 + mt * 16 + gid + half * 8;
            float* cp = C + (size_t)row * Nn + n0 + wn * 32 + tig * 2;
#pragma unroll
            for (int nt = 0; nt < 4; nt++) {
                float2 v;
                v.x = acc[mt][nt][half * 2 + 0] + bb[nt][0];
                v.y = acc[mt][nt][half * 2 + 1] + bb[nt][1];
                *(float2*)(cp + nt * 8) = v;
            }
        }
    }
#undef COPY_STAGE
}

// ---------------- prep: gen_weights + M = [web@cwE^T ; wrb@cwR^T] ----------
// One block per (b,h). g_M[bh][k][dp]: k<64 -> Mq(d=k,dp), k>=64 -> Mk(d=k-64,dp)
// Mq[d][dp] = sum_e web[d][e]*cw_w[dp][e]; Mk[d][dp] = sum_e wrb[d][e]*cw_w[dp][20+e]
#define PR_XH 0
#define PR_WE (PR_XH + RS*HD)          // 12800
#define PR_WR (PR_WE + RS*LR)          // +4000
#define PR_WEB (PR_WR + RS*LR)         // +4000
#define PR_WRB (PR_WEB + HD*LR)        // +1280
#define PR_CW  (PR_WRB + HD*LR)        // +1280
#define PR_TOT (PR_CW + HD*2*LR)       // +2560 = 25920 floats
__global__ __launch_bounds__(256) void prep_kernel(
    const float* __restrict__ x, const float* __restrict__ we,
    const float* __restrict__ wr, const float* __restrict__ cw_w,
    float* __restrict__ gM)
{
    extern __shared__ float s[];
    const int bh = blockIdx.x;
    const int b = bh >> 4, h = bh & 15;
    const int tid = threadIdx.x;
    const double step = (double)(SEQ - 1) / (double)(RS - 1);

    // load xh[r][d], we, wr, cw
    for (int i = tid; i < RS * HD; i += 256) {
        int r = i >> 6, d = i & 63;
        int idx = (r == RS - 1) ? (SEQ - 1) : (int)((double)r * step);
        s[PR_XH + i] = x[((size_t)b * SEQ + idx) * CH + h * HD + d];
    }
    for (int i = tid; i < RS * LR; i += 256) {
        s[PR_WE + i] = we[h * RS * LR + i];
        s[PR_WR + i] = wr[h * RS * LR + i];
    }
    for (int i = tid; i < HD * 2 * LR; i += 256)
        s[PR_CW + i] = cw_w[i];
    __syncthreads();

    // web[d][e] = sum_r xh[r][d]*we[r][e]  (units: 16 d4-groups x 20 e)
    for (int u = tid; u < 16 * LR; u += 256) {
        int d4 = (u & 15) * 4, e = u >> 4;
        float aE[4] = {0, 0, 0, 0}, aR[4] = {0, 0, 0, 0};
        for (int r = 0; r < RS; r++) {
            float4 xv = *(const float4*)&s[PR_XH + r * HD + d4];
            float wev = s[PR_WE + r * LR + e];
            float wrv = s[PR_WR + r * LR + e];
            aE[0] += xv.x * wev; aE[1] += xv.y * wev;
            aE[2] += xv.z * wev; aE[3] += xv.w * wev;
            aR[0] += xv.x * wrv; aR[1] += xv.y * wrv;
            aR[2] += xv.z * wrv; aR[3] += xv.w * wrv;
        }
#pragma unroll
        for (int j = 0; j < 4; j++) {
            s[PR_WEB + (d4 + j) * LR + e] = aE[j];
            s[PR_WRB + (d4 + j) * LR + e] = aR[j];
        }
    }
    __syncthreads();

    // M build
    for (int o = tid; o < HD * HD; o += 256) {
        int dp = o >> 6, d = o & 63;
        float mq = 0.f, mk = 0.f;
#pragma unroll
        for (int e = 0; e < LR; e++) {
            mq += s[PR_WEB + d * LR + e] * s[PR_CW + dp * 2 * LR + e];
            mk += s[PR_WRB + d * LR + e] * s[PR_CW + dp * 2 * LR + LR + e];
        }
        gM[((size_t)bh * 128 + d) * HD + dp]      = mq;
        gM[((size_t)bh * 128 + 64 + d) * HD + dp] = mk;
    }
}

// ---------------- normalize + transpose: qkn[bh][k][n] ----------------
// k<64: qn[d=k], k>=64: kn[d=k-64]. Block: (bh, 32-row n tile), 256 thr.
__global__ __launch_bounds__(256) void norm_kernel(
    const float* __restrict__ qk, float* __restrict__ qkn)
{
    __shared__ float sT[128][33];
    const int bh = blockIdx.x >> 6;
    const int n0 = (blockIdx.x & 63) * 32;
    const int b = bh >> 4, h = bh & 15;
    const int tid = threadIdx.x, w = tid >> 5, lane = tid & 31;

#pragma unroll
    for (int r = 0; r < 4; r++) {
        int nl = w * 4 + r;
        int n = n0 + nl;
        size_t base = ((size_t)b * SEQ + n) * QKW + h * HD;
        float2 qv = *(const float2*)(qk + base + lane * 2);
        float2 kv = *(const float2*)(qk + base + CH + lane * 2);
        float qs = qv.x * qv.x + qv.y * qv.y;
        float ks = kv.x * kv.x + kv.y * kv.y;
#pragma unroll
        for (int o = 16; o > 0; o >>= 1) {
            qs += __shfl_xor_sync(0xffffffffu, qs, o);
            ks += __shfl_xor_sync(0xffffffffu, ks, o);
        }
        float qsc = 1.f / fmaxf(sqrtf(qs), 1e-12f);
        float ksc = 1.f / fmaxf(sqrtf(ks), 1e-12f);
        sT[lane * 2][nl]      = qv.x * qsc;
        sT[lane * 2 + 1][nl]  = qv.y * qsc;
        sT[64 + lane * 2][nl]     = kv.x * ksc;
        sT[64 + lane * 2 + 1][nl] = kv.y * ksc;
    }
    __syncthreads();
    for (int i = tid; i < 128 * 32; i += 256) {
        int k = i >> 5, nl = i & 31;
        qkn[((size_t)bh * 128 + k) * SEQ + n0 + nl] = sT[k][nl];
    }
}

// ---------------- score2b: attn[b,h] = [qn|kn] @ M + cw_b ----------------
// Block: (128-row n tile, bh). Output 128x64, thread microtile 8x4.
__global__ __launch_bounds__(256) void score2b_kernel(
    const float* __restrict__ qkn, const float* __restrict__ gM,
    const float* __restrict__ cw_b, float* __restrict__ attn)
{
    __shared__ float sA[128][132];   // [k][n-local]
    __shared__ float sB[128][68];    // [k][dp]
    const int bh = blockIdx.y;
    const int b = bh >> 4, h = bh & 15;
    const int n0 = blockIdx.x * 128;
    const int tid = threadIdx.x;
    const int tm = tid >> 4, tn = tid & 15;   // rows tm*8.., cols tn*4..

    for (int i = tid; i < 128 * 32; i += 256) {
        int k = i >> 5, c4 = (i & 31) * 4;
        float4 v = *(const float4*)(qkn + ((size_t)bh * 128 + k) * SEQ + n0 + c4);
        *(float4*)&sA[k][c4] = v;
    }
    for (int i = tid; i < 128 * 16; i += 256) {
        int k = i >> 4, c4 = (i & 15) * 4;
        float4 v = *(const float4*)(gM + ((size_t)bh * 128 + k) * HD + c4);
        *(float4*)&sB[k][c4] = v;
    }
    __syncthreads();

    float acc[8][4];
#pragma unroll
    for (int i = 0; i < 8; i++)
#pragma unroll
        for (int j = 0; j < 4; j++) acc[i][j] = 0.f;

#pragma unroll 4
    for (int k = 0; k < 128; k++) {
        float4 a0 = *(const float4*)&sA[k][tm * 8];
        float4 a1 = *(const float4*)&sA[k][tm * 8 + 4];
        float4 bv = *(const float4*)&sB[k][tn * 4];
        float av[8] = {a0.x, a0.y, a0.z, a0.w, a1.x, a1.y, a1.z, a1.w};
        float bb[4] = {bv.x, bv.y, bv.z, bv.w};
#pragma unroll
        for (int i = 0; i < 8; i++)
#pragma unroll
            for (int j = 0; j < 4; j++)
                acc[i][j] += av[i] * bb[j];
    }

    float4 bias = *(const float4*)(cw_b + tn * 4);
    float bj[4] = {bias.x, bias.y, bias.z, bias.w};
#pragma unroll
    for (int i = 0; i < 8; i++) {
        int n = n0 + tm * 8 + i;
        float* op = attn + ((size_t)b * SEQ + n) * CH + h * HD + tn * 4;
        float4 v;
        v.x = tf32r(acc[i][0] + bj[0]);
        v.y = tf32r(acc[i][1] + bj[1]);
        v.z = tf32r(acc[i][2] + bj[2]);
        v.w = tf32r(acc[i][3] + bj[3]);
        *(float4*)op = v;
    }
}

// ---------------- launch ----------------
extern "C" void kernel_launch(void* const* d_in, const int* in_sizes, int n_in,
                              void* d_out, int out_size)
{
    const float* x      = (const float*)d_in[0];
    const float* qk_w   = (const float*)d_in[1];
    const float* proj_w = (const float*)d_in[2];
    const float* proj_b = (const float*)d_in[3];
    const float* we     = (const float*)d_in[4];
    const float* wr     = (const float*)d_in[5];
    const float* cw_w   = (const float*)d_in[6];
    const float* cw_b   = (const float*)d_in[7];
    float* out = (float*)d_out;

    float *qkbuf, *attnbuf, *xr, *qkwr, *pwr, *qkn, *gM;
    cudaGetSymbolAddress((void**)&qkbuf,  g_qk);
    cudaGetSymbolAddress((void**)&attnbuf, g_attn);
    cudaGetSymbolAddress((void**)&xr,   g_xr);
    cudaGetSymbolAddress((void**)&qkwr, g_qkwr);
    cudaGetSymbolAddress((void**)&pwr,  g_pwr);
    cudaGetSymbolAddress((void**)&qkn,  g_qkn);
    cudaGetSymbolAddress((void**)&gM,   g_M);

    const int smem_bytes = 3 * STAGE_FLT * 4;
    cudaFuncSetAttribute(gemm_tf32,
                         cudaFuncAttributeMaxDynamicSharedMemorySize, smem_bytes);
    const int prep_smem = PR_TOT * 4;
    cudaFuncSetAttribute(prep_kernel,
                         cudaFuncAttributeMaxDynamicSharedMemorySize, prep_smem);

    round_tf32<<<(MTOT * CH / 4) / 256, 256>>>(x, xr, MTOT * CH / 4);
    round_tf32<<<(QKW * CH / 4) / 256, 256>>>(qk_w, qkwr, QKW * CH / 4);
    round_tf32<<<(CH * CH / 4) / 256, 256>>>(proj_w, pwr, CH * CH / 4);

    // 1) qk = x @ qk_w.T
    {
        dim3 grid(QKW / 128, MTOT / 128);
        gemm_tf32<<<grid, 256, smem_bytes>>>(xr, qkwr, nullptr, qkbuf, QKW);
    }
    // 2) prep: web/wrb -> M  (independent of gemm1)
    prep_kernel<<<NBH, 256, prep_smem>>>(x, we, wr, cw_w, gM);
    // 3) normalize + transpose
    norm_kernel<<<NBH * (SEQ / 32), 256>>>(qkbuf, qkn);
    // 4) attn = [qn|kn] @ M + cw_b  (written tf32-rounded)
    {
        dim3 grid(SEQ / 128, NBH);
        score2b_kernel<<<grid, 256>>>(qkn, gM, cw_b, attnbuf);
    }
    // 5) out = attn @ proj_w.T + proj_b
    {
        dim3 grid(CH / 128, MTOT / 128);
        gemm_tf32<<<grid, 256, smem_bytes>>>(attnbuf, pwr, proj_b, out, CH);
    }
}

// round 7
// speedup vs baseline: 3.3945x; 1.1355x over previous
#include <cuda_runtime.h>
#include <cstdint>
#include <math.h>

// ---------------- problem constants ----------------
#define BCH 4
#define SEQ 2048
#define CH  1024
#define NH  16
#define HD  64
#define LR  20
#define RS  200
#define QKW (2*CH)
#define MTOT (BCH*SEQ)    // 8192
#define BK   32
#define NSTAGE (CH/BK)    // 32
#define STAGE_FLT (2*128*32)   // 8192 floats = 32 KB per stage (XOR swizzle, no pad)
#define NBH (BCH*NH)      // 64

// ---------------- scratch (device globals) ----------------
__device__ __align__(256) float g_qk[(size_t)MTOT * QKW];
__device__ __align__(256) float g_attn[(size_t)MTOT * CH];
__device__ __align__(256) float g_xr[(size_t)MTOT * CH];
__device__ __align__(256) float g_qkwr[(size_t)QKW * CH];
__device__ __align__(256) float g_pwr[(size_t)CH * CH];
__device__ __align__(256) float g_qkn[(size_t)NBH * 128 * SEQ];  // [bh][k][n]
__device__ __align__(256) float g_M[(size_t)NBH * 128 * HD];     // [bh][k][dp]

// ---------------- helpers ----------------
__device__ __forceinline__ float tf32r(float x) {
    float y;
    asm("cvt.rna.tf32.f32 %0, %1;" : "=f"(y) : "f"(x));
    return y;
}
__device__ __forceinline__ uint32_t smem_u32(const void* p) {
    uint32_t a;
    asm("{ .reg .u64 t; cvta.to.shared.u64 t, %1; cvt.u32.u64 %0, t; }"
        : "=r"(a) : "l"(p));
    return a;
}
#define CP_ASYNC16(dst, src) \
    asm volatile("cp.async.cg.shared.global [%0], [%1], 16;" :: "r"(dst), "l"(src))
#define CP_COMMIT() asm volatile("cp.async.commit_group;" ::: "memory")
#define CP_WAIT1()  asm volatile("cp.async.wait_group 1;" ::: "memory")

__device__ __forceinline__ void mma8(float* d, const float* a, const float* b) {
    asm volatile(
        "mma.sync.aligned.m16n8k8.row.col.f32.tf32.tf32.f32 "
        "{%0,%1,%2,%3}, {%4,%5,%6,%7}, {%8,%9}, {%0,%1,%2,%3};"
        : "+f"(d[0]), "+f"(d[1]), "+f"(d[2]), "+f"(d[3])
        : "r"(__float_as_uint(a[0])), "r"(__float_as_uint(a[1])),
          "r"(__float_as_uint(a[2])), "r"(__float_as_uint(a[3])),
          "r"(__float_as_uint(b[0])), "r"(__float_as_uint(b[1])));
}

// ---------------- tf32 rounding pass ----------------
__global__ __launch_bounds__(256) void round_tf32(
    const float* __restrict__ src, float* __restrict__ dst, int n4)
{
    int i = blockIdx.x * 256 + threadIdx.x;
    if (i >= n4) return;
    float4 v = ((const float4*)src)[i];
    v.x = tf32r(v.x); v.y = tf32r(v.y); v.z = tf32r(v.z); v.w = tf32r(v.w);
    ((float4*)dst)[i] = v;
}

// ---------------- tf32 tensor GEMM ----------------
// C[m,n] = sum_k A[m,k]*B[n,k] (+bias[n]).  Row-major, K=1024, pre-rounded.
// CTA 128x128, 256 thr (2x4 warps, warp tile 64x32), BK=32.
// 3-stage cp.async, ONE barrier per stage, XOR-swizzled smem (32-float rows,
// 16B chunk c stored at c ^ (row&7)).
__global__ __launch_bounds__(256, 2) void gemm_tf32(
    const float* __restrict__ A, const float* __restrict__ B,
    const float* __restrict__ bias, float* __restrict__ C, int Nn)
{
    extern __shared__ float sm[];
    const uint32_t sbase = smem_u32(sm);

    const int tid = threadIdx.x;
    const int wid = tid >> 5, lane = tid & 31;
    const int wm = wid >> 2;          // 0..1
    const int wn = wid & 3;           // 0..3
    const int gid = lane >> 2;        // 0..7
    const int tig = lane & 3;         // 0..3
    const int m0 = blockIdx.y * 128, n0 = blockIdx.x * 128;

#define COPY_STAGE(s) do {                                                     \
        const int _k0 = (s) * BK;                                              \
        const uint32_t _db = sbase + ((s) % 3) * (STAGE_FLT * 4);              \
        _Pragma("unroll")                                                      \
        for (int _i = 0; _i < 8; _i++) {                                       \
            int _id  = _i * 256 + tid;                                         \
            int _mat = _id >> 10;                                              \
            int _row = (_id >> 3) & 127;                                       \
            int _ch  = _id & 7;                                                \
            const float* _src = (_mat ? (B + (size_t)(n0 + _row) * CH)         \
                                      : (A + (size_t)(m0 + _row) * CH))        \
                                + _k0 + _ch * 4;                               \
            uint32_t _dst = _db + (uint32_t)(_mat * 4096 + _row * 32 +         \
                                   ((_ch ^ (_row & 7)) << 2)) * 4u;            \
            CP_ASYNC16(_dst, _src);                                            \
        }                                                                      \
    } while (0)

    COPY_STAGE(0); CP_COMMIT();
    COPY_STAGE(1); CP_COMMIT();

    float acc[4][4][4];
#pragma unroll
    for (int mt = 0; mt < 4; mt++)
#pragma unroll
        for (int nt = 0; nt < 4; nt++)
#pragma unroll
            for (int r = 0; r < 4; r++) acc[mt][nt][r] = 0.f;

    // per-thread fragment base offsets (floats)
    int mbase[4], nbase[4];
#pragma unroll
    for (int mt = 0; mt < 4; mt++)
        mbase[mt] = (wm * 64 + mt * 16 + gid) * 32 + tig;
#pragma unroll
    for (int nt = 0; nt < 4; nt++)
        nbase[nt] = (wn * 32 + nt * 8 + gid) * 32 + tig;

    for (int c = 0; c < NSTAGE; c++) {
        CP_WAIT1();
        __syncthreads();
        if (c + 2 < NSTAGE) COPY_STAGE(c + 2);
        CP_COMMIT();

        const float* As = sm + (c % 3) * STAGE_FLT;
        const float* Bs = As + 4096;

#pragma unroll
        for (int ks = 0; ks < BK; ks += 8) {
            const int x0 = (((ks >> 2)     ) ^ gid) << 2;
            const int x1 = (((ks >> 2) + 1) ^ gid) << 2;
            float af[4][4], bf[4][2];
#pragma unroll
            for (int mt = 0; mt < 4; mt++) {
                af[mt][0] = As[mbase[mt] + x0];
                af[mt][1] = As[mbase[mt] + 256 + x0];   // m+8
                af[mt][2] = As[mbase[mt] + x1];
                af[mt][3] = As[mbase[mt] + 256 + x1];
            }
#pragma unroll
            for (int nt = 0; nt < 4; nt++) {
                bf[nt][0] = Bs[nbase[nt] + x0];
                bf[nt][1] = Bs[nbase[nt] + x1];
            }
#pragma unroll
            for (int mt = 0; mt < 4; mt++)
#pragma unroll
                for (int nt = 0; nt < 4; nt++)
                    mma8(acc[mt][nt], af[mt], bf[nt]);
        }
    }

    // ---- epilogue ----
    float bb[4][2];
#pragma unroll
    for (int nt = 0; nt < 4; nt++) {
        int col = n0 + wn * 32 + nt * 8 + tig * 2;
        bb[nt][0] = bias ? bias[col]     : 0.f;
        bb[nt][1] = bias ? bias[col + 1] : 0.f;
    }
#pragma unroll
    for (int mt = 0; mt < 4; mt++) {
#pragma unroll
        for (int half = 0; half < 2; half++) {
            int row = m0 + wm * 64 + mt * 16 + gid + half * 8;
            float* cp = C + (size_t)row * Nn + n0 + wn * 32 + tig * 2;
#pragma unroll
            for (int nt = 0; nt < 4; nt++) {
                float2 v;
                v.x = acc[mt][nt][half * 2 + 0] + bb[nt][0];
                v.y = acc[mt][nt][half * 2 + 1] + bb[nt][1];
                *(float2*)(cp + nt * 8) = v;
            }
        }
    }
#undef COPY_STAGE
}

// ---------------- prep: gen_weights + M = [web@cwE^T ; wrb@cwR^T] ----------
#define PR_XH 0
#define PR_WE (PR_XH + RS*HD)
#define PR_WR (PR_WE + RS*LR)
#define PR_WEB (PR_WR + RS*LR)
#define PR_WRB (PR_WEB + HD*LR)
#define PR_CW  (PR_WRB + HD*LR)
#define PR_TOT (PR_CW + HD*2*LR)
__global__ __launch_bounds__(256) void prep_kernel(
    const float* __restrict__ x, const float* __restrict__ we,
    const float* __restrict__ wr, const float* __restrict__ cw_w,
    float* __restrict__ gM)
{
    extern __shared__ float s[];
    const int bh = blockIdx.x;
    const int b = bh >> 4, h = bh & 15;
    const int tid = threadIdx.x;
    const double step = (double)(SEQ - 1) / (double)(RS - 1);

    for (int i = tid; i < RS * HD; i += 256) {
        int r = i >> 6, d = i & 63;
        int idx = (r == RS - 1) ? (SEQ - 1) : (int)((double)r * step);
        s[PR_XH + i] = x[((size_t)b * SEQ + idx) * CH + h * HD + d];
    }
    for (int i = tid; i < RS * LR; i += 256) {
        s[PR_WE + i] = we[h * RS * LR + i];
        s[PR_WR + i] = wr[h * RS * LR + i];
    }
    for (int i = tid; i < HD * 2 * LR; i += 256)
        s[PR_CW + i] = cw_w[i];
    __syncthreads();

    for (int u = tid; u < 16 * LR; u += 256) {
        int d4 = (u & 15) * 4, e = u >> 4;
        float aE[4] = {0, 0, 0, 0}, aR[4] = {0, 0, 0, 0};
        for (int r = 0; r < RS; r++) {
            float4 xv = *(const float4*)&s[PR_XH + r * HD + d4];
            float wev = s[PR_WE + r * LR + e];
            float wrv = s[PR_WR + r * LR + e];
            aE[0] += xv.x * wev; aE[1] += xv.y * wev;
            aE[2] += xv.z * wev; aE[3] += xv.w * wev;
            aR[0] += xv.x * wrv; aR[1] += xv.y * wrv;
            aR[2] += xv.z * wrv; aR[3] += xv.w * wrv;
        }
#pragma unroll
        for (int j = 0; j < 4; j++) {
            s[PR_WEB + (d4 + j) * LR + e] = aE[j];
            s[PR_WRB + (d4 + j) * LR + e] = aR[j];
        }
    }
    __syncthreads();

    for (int o = tid; o < HD * HD; o += 256) {
        int dp = o >> 6, d = o & 63;
        float mq = 0.f, mk = 0.f;
#pragma unroll
        for (int e = 0; e < LR; e++) {
            mq += s[PR_WEB + d * LR + e] * s[PR_CW + dp * 2 * LR + e];
            mk += s[PR_WRB + d * LR + e] * s[PR_CW + dp * 2 * LR + LR + e];
        }
        gM[((size_t)bh * 128 + d) * HD + dp]      = mq;
        gM[((size_t)bh * 128 + 64 + d) * HD + dp] = mk;
    }
}

// ---------------- normalize + transpose: qkn[bh][k][n] ----------------
__global__ __launch_bounds__(256) void norm_kernel(
    const float* __restrict__ qk, float* __restrict__ qkn)
{
    __shared__ float sT[128][33];
    const int bh = blockIdx.x >> 6;
    const int n0 = (blockIdx.x & 63) * 32;
    const int b = bh >> 4, h = bh & 15;
    const int tid = threadIdx.x, w = tid >> 5, lane = tid & 31;

#pragma unroll
    for (int r = 0; r < 4; r++) {
        int nl = w * 4 + r;
        int n = n0 + nl;
        size_t base = ((size_t)b * SEQ + n) * QKW + h * HD;
        float2 qv = *(const float2*)(qk + base + lane * 2);
        float2 kv = *(const float2*)(qk + base + CH + lane * 2);
        float qs = qv.x * qv.x + qv.y * qv.y;
        float ks = kv.x * kv.x + kv.y * kv.y;
#pragma unroll
        for (int o = 16; o > 0; o >>= 1) {
            qs += __shfl_xor_sync(0xffffffffu, qs, o);
            ks += __shfl_xor_sync(0xffffffffu, ks, o);
        }
        float qsc = 1.f / fmaxf(sqrtf(qs), 1e-12f);
        float ksc = 1.f / fmaxf(sqrtf(ks), 1e-12f);
        sT[lane * 2][nl]      = qv.x * qsc;
        sT[lane * 2 + 1][nl]  = qv.y * qsc;
        sT[64 + lane * 2][nl]     = kv.x * ksc;
        sT[64 + lane * 2 + 1][nl] = kv.y * ksc;
    }
    __syncthreads();
    for (int i = tid; i < 128 * 32; i += 256) {
        int k = i >> 5, nl = i & 31;
        qkn[((size_t)bh * 128 + k) * SEQ + n0 + nl] = sT[k][nl];
    }
}

// ---------------- score2b: attn[b,h] = [qn|kn] @ M + cw_b ----------------
__global__ __launch_bounds__(256) void score2b_kernel(
    const float* __restrict__ qkn, const float* __restrict__ gM,
    const float* __restrict__ cw_b, float* __restrict__ attn)
{
    __shared__ float sA[128][132];
    __shared__ float sB[128][68];
    const int bh = blockIdx.y;
    const int b = bh >> 4, h = bh & 15;
    const int n0 = blockIdx.x * 128;
    const int tid = threadIdx.x;
    const int tm = tid >> 4, tn = tid & 15;

    for (int i = tid; i < 128 * 32; i += 256) {
        int k = i >> 5, c4 = (i & 31) * 4;
        float4 v = *(const float4*)(qkn + ((size_t)bh * 128 + k) * SEQ + n0 + c4);
        *(float4*)&sA[k][c4] = v;
    }
    for (int i = tid; i < 128 * 16; i += 256) {
        int k = i >> 4, c4 = (i & 15) * 4;
        float4 v = *(const float4*)(gM + ((size_t)bh * 128 + k) * HD + c4);
        *(float4*)&sB[k][c4] = v;
    }
    __syncthreads();

    float acc[8][4];
#pragma unroll
    for (int i = 0; i < 8; i++)
#pragma unroll
        for (int j = 0; j < 4; j++) acc[i][j] = 0.f;

#pragma unroll 4
    for (int k = 0; k < 128; k++) {
        float4 a0 = *(const float4*)&sA[k][tm * 8];
        float4 a1 = *(const float4*)&sA[k][tm * 8 + 4];
        float4 bv = *(const float4*)&sB[k][tn * 4];
        float av[8] = {a0.x, a0.y, a0.z, a0.w, a1.x, a1.y, a1.z, a1.w};
        float bb[4] = {bv.x, bv.y, bv.z, bv.w};
#pragma unroll
        for (int i = 0; i < 8; i++)
#pragma unroll
            for (int j = 0; j < 4; j++)
                acc[i][j] += av[i] * bb[j];
    }

    float4 bias = *(const float4*)(cw_b + tn * 4);
    float bj[4] = {bias.x, bias.y, bias.z, bias.w};
#pragma unroll
    for (int i = 0; i < 8; i++) {
        int n = n0 + tm * 8 + i;
        float* op = attn + ((size_t)b * SEQ + n) * CH + h * HD + tn * 4;
        float4 v;
        v.x = tf32r(acc[i][0] + bj[0]);
        v.y = tf32r(acc[i][1] + bj[1]);
        v.z = tf32r(acc[i][2] + bj[2]);
        v.w = tf32r(acc[i][3] + bj[3]);
        *(float4*)op = v;
    }
}

// ---------------- launch ----------------
extern "C" void kernel_launch(void* const* d_in, const int* in_sizes, int n_in,
                              void* d_out, int out_size)
{
    const float* x      = (const float*)d_in[0];
    const float* qk_w   = (const float*)d_in[1];
    const float* proj_w = (const float*)d_in[2];
    const float* proj_b = (const float*)d_in[3];
    const float* we     = (const float*)d_in[4];
    const float* wr     = (const float*)d_in[5];
    const float* cw_w   = (const float*)d_in[6];
    const float* cw_b   = (const float*)d_in[7];
    float* out = (float*)d_out;

    float *qkbuf, *attnbuf, *xr, *qkwr, *pwr, *qkn, *gM;
    cudaGetSymbolAddress((void**)&qkbuf,  g_qk);
    cudaGetSymbolAddress((void**)&attnbuf, g_attn);
    cudaGetSymbolAddress((void**)&xr,   g_xr);
    cudaGetSymbolAddress((void**)&qkwr, g_qkwr);
    cudaGetSymbolAddress((void**)&pwr,  g_pwr);
    cudaGetSymbolAddress((void**)&qkn,  g_qkn);
    cudaGetSymbolAddress((void**)&gM,   g_M);

    const int smem_bytes = 3 * STAGE_FLT * 4;   // 98304
    cudaFuncSetAttribute(gemm_tf32,
                         cudaFuncAttributeMaxDynamicSharedMemorySize, smem_bytes);
    const int prep_smem = PR_TOT * 4;
    cudaFuncSetAttribute(prep_kernel,
                         cudaFuncAttributeMaxDynamicSharedMemorySize, prep_smem);

    round_tf32<<<(MTOT * CH / 4) / 256, 256>>>(x, xr, MTOT * CH / 4);
    round_tf32<<<(QKW * CH / 4) / 256, 256>>>(qk_w, qkwr, QKW * CH / 4);
    round_tf32<<<(CH * CH / 4) / 256, 256>>>(proj_w, pwr, CH * CH / 4);

    // 1) qk = x @ qk_w.T
    {
        dim3 grid(QKW / 128, MTOT / 128);
        gemm_tf32<<<grid, 256, smem_bytes>>>(xr, qkwr, nullptr, qkbuf, QKW);
    }
    // 2) prep (independent of gemm1)
    prep_kernel<<<NBH, 256, prep_smem>>>(x, we, wr, cw_w, gM);
    // 3) normalize + transpose
    norm_kernel<<<NBH * (SEQ / 32), 256>>>(qkbuf, qkn);
    // 4) attn = [qn|kn] @ M + cw_b
    {
        dim3 grid(SEQ / 128, NBH);
        score2b_kernel<<<grid, 256>>>(qkn, gM, cw_b, attnbuf);
    }
    // 5) out = attn @ proj_w.T + proj_b
    {
        dim3 grid(CH / 128, MTOT / 128);
        gemm_tf32<<<grid, 256, smem_bytes>>>(attnbuf, pwr, proj_b, out, CH);
    }
}

// round 8
// speedup vs baseline: 3.5873x; 1.0568x over previous
#include <cuda_runtime.h>
#include <cstdint>
#include <math.h>

// ---------------- problem constants ----------------
#define BCH 4
#define SEQ 2048
#define CH  1024
#define NH  16
#define HD  64
#define LR  20
#define RS  200
#define QKW (2*CH)
#define MTOT (BCH*SEQ)    // 8192
#define BK   32
#define STAGE_FLT (2*128*32)   // 32 KB per pipeline stage
#define NBH (BCH*NH)      // 64
#define KS2  640               // rank-structured K for the output gemm

// ---------------- scratch (device globals) ----------------
__device__ __align__(256) float g_xr[(size_t)MTOT * CH];
__device__ __align__(256) float g_qkwr[(size_t)QKW * CH];
__device__ __align__(256) float g_qkn[(size_t)NBH * 128 * SEQ];  // [bh][k][n]
__device__ __align__(256) float g_wc[(size_t)NBH * 128 * 40];    // [bh][k][j] zero-padded
__device__ __align__(256) float g_S[(size_t)MTOT * KS2];         // [b*n][h*40+j]
__device__ __align__(256) float g_Bg[(size_t)CH * KS2];          // [o][hj]
__device__ __align__(256) float g_obias[CH];

// ---------------- helpers ----------------
__device__ __forceinline__ float tf32r(float x) {
    float y;
    asm("cvt.rna.tf32.f32 %0, %1;" : "=f"(y) : "f"(x));
    return y;
}
__device__ __forceinline__ uint32_t smem_u32(const void* p) {
    uint32_t a;
    asm("{ .reg .u64 t; cvta.to.shared.u64 t, %1; cvt.u32.u64 %0, t; }"
        : "=r"(a) : "l"(p));
    return a;
}
#define CP_ASYNC16(dst, src) \
    asm volatile("cp.async.cg.shared.global [%0], [%1], 16;" :: "r"(dst), "l"(src))
#define CP_COMMIT() asm volatile("cp.async.commit_group;" ::: "memory")
#define CP_WAIT1()  asm volatile("cp.async.wait_group 1;" ::: "memory")

__device__ __forceinline__ void mma8(float* d, const float* a, const float* b) {
    asm volatile(
        "mma.sync.aligned.m16n8k8.row.col.f32.tf32.tf32.f32 "
        "{%0,%1,%2,%3}, {%4,%5,%6,%7}, {%8,%9}, {%0,%1,%2,%3};"
        : "+f"(d[0]), "+f"(d[1]), "+f"(d[2]), "+f"(d[3])
        : "r"(__float_as_uint(a[0])), "r"(__float_as_uint(a[1])),
          "r"(__float_as_uint(a[2])), "r"(__float_as_uint(a[3])),
          "r"(__float_as_uint(b[0])), "r"(__float_as_uint(b[1])));
}

// shared mainloop pieces -----------------------------------------------------
#define GEMM_PROLOG()                                                          \
    const int tid = threadIdx.x;                                               \
    const int wid = tid >> 5, lane = tid & 31;                                 \
    const int wm = wid >> 2;                                                   \
    const int wn = wid & 3;                                                    \
    const int gid = lane >> 2;                                                 \
    const int tig = lane & 3;                                                  \
    (void)lane;

#define COPY_STAGE(s, Kdim) do {                                               \
        const int _k0 = (s) * BK;                                              \
        const uint32_t _db = sbase + ((s) % 3) * (STAGE_FLT * 4);              \
        _Pragma("unroll")                                                      \
        for (int _i = 0; _i < 8; _i++) {                                       \
            int _id  = _i * 256 + tid;                                         \
            int _mat = _id >> 10;                                              \
            int _row = (_id >> 3) & 127;                                       \
            int _ch  = _id & 7;                                                \
            const float* _src = (_mat ? (B + (size_t)(n0 + _row) * (Kdim))     \
                                      : (A + (size_t)(m0 + _row) * (Kdim)))    \
                                + _k0 + _ch * 4;                               \
            uint32_t _dst = _db + (uint32_t)(_mat * 4096 + _row * 32 +         \
                                   ((_ch ^ (_row & 7)) << 2)) * 4u;            \
            CP_ASYNC16(_dst, _src);                                            \
        }                                                                      \
    } while (0)

#define GEMM_MAINLOOP(Kdim, nst)                                               \
    COPY_STAGE(0, Kdim); CP_COMMIT();                                          \
    COPY_STAGE(1, Kdim); CP_COMMIT();                                          \
    float acc[4][4][4];                                                        \
    _Pragma("unroll")                                                          \
    for (int mt = 0; mt < 4; mt++)                                             \
        _Pragma("unroll")                                                      \
        for (int nt = 0; nt < 4; nt++)                                         \
            _Pragma("unroll")                                                  \
            for (int r = 0; r < 4; r++) acc[mt][nt][r] = 0.f;                  \
    int mbase[4], nbase[4];                                                    \
    _Pragma("unroll")                                                          \
    for (int mt = 0; mt < 4; mt++)                                             \
        mbase[mt] = (wm * 64 + mt * 16 + gid) * 32 + tig;                      \
    _Pragma("unroll")                                                          \
    for (int nt = 0; nt < 4; nt++)                                             \
        nbase[nt] = (wn * 32 + nt * 8 + gid) * 32 + tig;                       \
    for (int c = 0; c < (nst); c++) {                                          \
        CP_WAIT1();                                                            \
        __syncthreads();                                                       \
        if (c + 2 < (nst)) COPY_STAGE(c + 2, Kdim);                            \
        CP_COMMIT();                                                           \
        const float* As = sm + (c % 3) * STAGE_FLT;                            \
        const float* Bs = As + 4096;                                           \
        _Pragma("unroll")                                                      \
        for (int ks = 0; ks < BK; ks += 8) {                                   \
            const int x0 = (((ks >> 2)     ) ^ gid) << 2;                      \
            const int x1 = (((ks >> 2) + 1) ^ gid) << 2;                       \
            float af[4][4], bf[4][2];                                          \
            _Pragma("unroll")                                                  \
            for (int mt = 0; mt < 4; mt++) {                                   \
                af[mt][0] = As[mbase[mt] + x0];                                \
                af[mt][1] = As[mbase[mt] + 256 + x0];                          \
                af[mt][2] = As[mbase[mt] + x1];                                \
                af[mt][3] = As[mbase[mt] + 256 + x1];                          \
            }                                                                  \
            _Pragma("unroll")                                                  \
            for (int nt = 0; nt < 4; nt++) {                                   \
                bf[nt][0] = Bs[nbase[nt] + x0];                                \
                bf[nt][1] = Bs[nbase[nt] + x1];                                \
            }                                                                  \
            _Pragma("unroll")                                                  \
            for (int mt = 0; mt < 4; mt++)                                     \
                _Pragma("unroll")                                              \
                for (int nt = 0; nt < 4; nt++)                                 \
                    mma8(acc[mt][nt], af[mt], bf[nt]);                         \
        }                                                                      \
    }

// ---------------- round pass (x and qk_w in one launch) ----------------
__global__ __launch_bounds__(256) void round_all(
    const float* __restrict__ x, const float* __restrict__ qkw,
    float* __restrict__ xr, float* __restrict__ qkwr)
{
    const int X4 = MTOT * CH / 4;
    const int W4 = QKW * CH / 4;
    int i = blockIdx.x * 256 + threadIdx.x;
    if (i < X4) {
        float4 v = ((const float4*)x)[i];
        v.x = tf32r(v.x); v.y = tf32r(v.y); v.z = tf32r(v.z); v.w = tf32r(v.w);
        ((float4*)xr)[i] = v;
    } else if (i < X4 + W4) {
        int j = i - X4;
        float4 v = ((const float4*)qkw)[j];
        v.x = tf32r(v.x); v.y = tf32r(v.y); v.z = tf32r(v.z); v.w = tf32r(v.w);
        ((float4*)qkwr)[j] = v;
    }
}

// ---------------- gemm_qk: qk tile + fused normalize + transpose ------------
// Writes qkn[bh][kdim][n] (q rows kdim<64, k rows kdim>=64), normalized.
__global__ __launch_bounds__(256, 2) void gemm_qk(
    const float* __restrict__ A, const float* __restrict__ B,
    float* __restrict__ qkn)
{
    extern __shared__ float sm[];
    const uint32_t sbase = smem_u32(sm);
    GEMM_PROLOG();
    const int m0 = blockIdx.y * 128, n0 = blockIdx.x * 128;

    GEMM_MAINLOOP(CH, CH / BK);

    // ---- fused epilogue: transpose -> norms -> qkn ----
    __syncthreads();                       // everyone done with pipeline smem
    float* st = sm;                        // [128 col][132] (16B-aligned rows)
    float* snorm = sm + 128 * 132;         // [row][2]
#pragma unroll
    for (int mt = 0; mt < 4; mt++)
#pragma unroll
        for (int half = 0; half < 2; half++) {
            int row = wm * 64 + mt * 16 + gid + half * 8;
#pragma unroll
            for (int nt = 0; nt < 4; nt++) {
                int col = wn * 32 + nt * 8 + tig * 2;
                st[(col)     * 132 + row] = acc[mt][nt][half * 2 + 0];
                st[(col + 1) * 132 + row] = acc[mt][nt][half * 2 + 1];
            }
        }
    __syncthreads();
    {
        int r = tid & 127, hh = tid >> 7;
        float s = 0.f;
#pragma unroll 8
        for (int c = 0; c < 64; c++) {
            float v = st[(hh * 64 + c) * 132 + r];
            s += v * v;
        }
        snorm[r * 2 + hh] = 1.f / fmaxf(sqrtf(s), 1e-12f);
    }
    __syncthreads();

    const int b = (blockIdx.y * 128) >> 11;
    const int nseq0 = (blockIdx.y * 128) & 2047;
    const int c0 = blockIdx.x * 128;
    const int h0 = (c0 < 1024) ? (c0 >> 6) : ((c0 - 1024) >> 6);
    const int kbase = (c0 < 1024) ? 0 : 64;

    for (int it = 0; it < 16; it++) {
        int cl = wid + 8 * it;             // 0..127
        int hh = cl >> 6, d = cl & 63;
        int bh = b * NH + h0 + hh;
        int kdim = kbase + d;
        float4 v = *(const float4*)&st[cl * 132 + lane * 4];
        v.x *= snorm[(lane * 4 + 0) * 2 + hh];
        v.y *= snorm[(lane * 4 + 1) * 2 + hh];
        v.z *= snorm[(lane * 4 + 2) * 2 + hh];
        v.w *= snorm[(lane * 4 + 3) * 2 + hh];
        *(float4*)&qkn[((size_t)bh * 128 + kdim) * SEQ + nseq0 + lane * 4] = v;
    }
}

// ---------------- generic tf32 GEMM (runtime K) ----------------
__global__ __launch_bounds__(256, 2) void gemm_tf32(
    const float* __restrict__ A, const float* __restrict__ B,
    const float* __restrict__ bias, float* __restrict__ C,
    int Nn, int K)
{
    extern __shared__ float sm[];
    const uint32_t sbase = smem_u32(sm);
    GEMM_PROLOG();
    const int m0 = blockIdx.y * 128, n0 = blockIdx.x * 128;

    GEMM_MAINLOOP(K, K / BK);

    float bb[4][2];
#pragma unroll
    for (int nt = 0; nt < 4; nt++) {
        int col = n0 + wn * 32 + nt * 8 + tig * 2;
        bb[nt][0] = bias ? bias[col]     : 0.f;
        bb[nt][1] = bias ? bias[col + 1] : 0.f;
    }
#pragma unroll
    for (int mt = 0; mt < 4; mt++)
#pragma unroll
        for (int half = 0; half < 2; half++) {
            int row = m0 + wm * 64 + mt * 16 + gid + half * 8;
            float* cp = C + (size_t)row * Nn + n0 + wn * 32 + tig * 2;
#pragma unroll
            for (int nt = 0; nt < 4; nt++) {
                float2 v;
                v.x = acc[mt][nt][half * 2 + 0] + bb[nt][0];
                v.y = acc[mt][nt][half * 2 + 1] + bb[nt][1];
                *(float2*)(cp + nt * 8) = v;
            }
        }
}

// ---------------- prep: gen_weights -> zero-padded wc [bh][128][40] --------
#define PR_XH 0
#define PR_WE (PR_XH + RS*HD)
#define PR_WR (PR_WE + RS*LR)
#define PR_WEB (PR_WR + RS*LR)
#define PR_WRB (PR_WEB + HD*LR)
#define PR_TOT (PR_WRB + HD*LR)
__global__ __launch_bounds__(256) void prep_kernel(
    const float* __restrict__ x, const float* __restrict__ we,
    const float* __restrict__ wr, float* __restrict__ wc)
{
    extern __shared__ float s[];
    const int bh = blockIdx.x;
    const int b = bh >> 4, h = bh & 15;
    const int tid = threadIdx.x;
    const double step = (double)(SEQ - 1) / (double)(RS - 1);

    for (int i = tid; i < RS * HD; i += 256) {
        int r = i >> 6, d = i & 63;
        int idx = (r == RS - 1) ? (SEQ - 1) : (int)((double)r * step);
        s[PR_XH + i] = x[((size_t)b * SEQ + idx) * CH + h * HD + d];
    }
    for (int i = tid; i < RS * LR; i += 256) {
        s[PR_WE + i] = we[h * RS * LR + i];
        s[PR_WR + i] = wr[h * RS * LR + i];
    }
    __syncthreads();

    for (int u = tid; u < 16 * LR; u += 256) {
        int d4 = (u & 15) * 4, e = u >> 4;
        float aE[4] = {0, 0, 0, 0}, aR[4] = {0, 0, 0, 0};
        for (int r = 0; r < RS; r++) {
            float4 xv = *(const float4*)&s[PR_XH + r * HD + d4];
            float wev = s[PR_WE + r * LR + e];
            float wrv = s[PR_WR + r * LR + e];
            aE[0] += xv.x * wev; aE[1] += xv.y * wev;
            aE[2] += xv.z * wev; aE[3] += xv.w * wev;
            aR[0] += xv.x * wrv; aR[1] += xv.y * wrv;
            aR[2] += xv.z * wrv; aR[3] += xv.w * wrv;
        }
#pragma unroll
        for (int j = 0; j < 4; j++) {
            s[PR_WEB + (d4 + j) * LR + e] = aE[j];
            s[PR_WRB + (d4 + j) * LR + e] = aR[j];
        }
    }
    __syncthreads();

    // wc[k][j]: k<64 & j<20 -> web[k][j]; k>=64 & j>=20 -> wrb[k-64][j-20]; else 0
    for (int o = tid; o < 128 * 40; o += 256) {
        int k = o / 40, j = o % 40;
        float v = 0.f;
        if (k < 64 && j < LR)        v = s[PR_WEB + k * LR + j];
        else if (k >= 64 && j >= LR) v = s[PR_WRB + (k - 64) * LR + (j - LR)];
        wc[(size_t)bh * 128 * 40 + o] = v;
    }
}

// ---------------- gprep: Bg[o][h*40+j] = sum_dp proj_w[o][h*64+dp]*cw_w[dp][j]
__global__ __launch_bounds__(256) void gprep_kernel(
    const float* __restrict__ proj_w, const float* __restrict__ cw_w,
    float* __restrict__ Bg)
{
    __shared__ float s_cw[HD * 40];
    const int tid = threadIdx.x;
    for (int i = tid; i < HD * 40; i += 256) s_cw[i] = cw_w[i];
    __syncthreads();

    int idx = blockIdx.x * 256 + tid;
    int o = idx >> 4, h = idx & 15;
    float acc[40];
#pragma unroll
    for (int j = 0; j < 40; j++) acc[j] = 0.f;
    const float* pr = proj_w + (size_t)o * CH + h * HD;
    for (int dp = 0; dp < HD; dp++) {
        float pv = pr[dp];
#pragma unroll
        for (int j = 0; j < 40; j++) acc[j] += pv * s_cw[dp * 40 + j];
    }
    float* dst = Bg + (size_t)o * KS2 + h * 40;
#pragma unroll
    for (int j = 0; j < 40; j++) dst[j] = tf32r(acc[j]);
}

// ---------------- obias[o] = proj_b[o] + sum_c cw_b[c%64]*proj_w[o][c] -----
__global__ __launch_bounds__(256) void obias_kernel(
    const float* __restrict__ proj_w, const float* __restrict__ proj_b,
    const float* __restrict__ cw_b, float* __restrict__ obias)
{
    const int w = threadIdx.x >> 5, lane = threadIdx.x & 31;
    const int o = blockIdx.x * 8 + w;
    float s = 0.f;
    for (int c = lane; c < CH; c += 32)
        s += proj_w[(size_t)o * CH + c] * cw_b[c & 63];
#pragma unroll
    for (int off = 16; off > 0; off >>= 1)
        s += __shfl_xor_sync(0xffffffffu, s, off);
    if (lane == 0) obias[o] = proj_b[o] + s;
}

// ---------------- sgemm_S: S[b][n][h*40+j] = sum_k qkn[bh][k][n]*wc[bh][k][j]
// Block 128 thr per (bh, 128-n tile).
__global__ __launch_bounds__(128) void sgemm_S(
    const float* __restrict__ qkn, const float* __restrict__ wc,
    float* __restrict__ S)
{
    extern __shared__ float s[];
    float* qt = s;                 // [128 k][132 n]
    float* swc = s + 128 * 132;    // [128 k][40 j]
    float* stile = s;              // reuse qt region after compute: [128 n][40 j]

    const int bh = blockIdx.y;
    const int b = bh >> 4, h = bh & 15;
    const int n0 = blockIdx.x * 128;
    const int tid = threadIdx.x;

    for (int i = tid; i < 128 * 32; i += 128) {
        int k = i >> 5, c4 = (i & 31) * 4;
        float4 v = *(const float4*)&qkn[((size_t)bh * 128 + k) * SEQ + n0 + c4];
        *(float4*)&qt[k * 132 + c4] = v;
    }
    for (int i = tid; i < 128 * 40; i += 128)
        swc[i] = wc[(size_t)bh * 128 * 40 + i];
    __syncthreads();

    const int tn = tid & 15;       // n block of 8
    const int jg = tid >> 4;       // j block of 5
    float acc[8][5];
#pragma unroll
    for (int i = 0; i < 8; i++)
#pragma unroll
        for (int j = 0; j < 5; j++) acc[i][j] = 0.f;

    for (int k = 0; k < 128; k++) {
        float4 a0 = *(const float4*)&qt[k * 132 + tn * 8];
        float4 a1 = *(const float4*)&qt[k * 132 + tn * 8 + 4];
        float av[8] = {a0.x, a0.y, a0.z, a0.w, a1.x, a1.y, a1.z, a1.w};
        float wv[5];
#pragma unroll
        for (int j = 0; j < 5; j++) wv[j] = swc[k * 40 + jg * 5 + j];
#pragma unroll
        for (int i = 0; i < 8; i++)
#pragma unroll
            for (int j = 0; j < 5; j++)
                acc[i][j] += av[i] * wv[j];
    }
    __syncthreads();   // done with qt

#pragma unroll
    for (int i = 0; i < 8; i++)
#pragma unroll
        for (int j = 0; j < 5; j++)
            stile[(tn * 8 + i) * 40 + jg * 5 + j] = tf32r(acc[i][j]);
    __syncthreads();

    // coalesced store: warp per row, cols lane and 32+lane
    const int w = tid >> 5, lane = tid & 31;
    for (int it = 0; it < 32; it++) {
        int r = w + 4 * it;
        float* dst = S + ((size_t)b * SEQ + n0 + r) * KS2 + h * 40;
        dst[lane] = stile[r * 40 + lane];
        if (lane < 8) dst[32 + lane] = stile[r * 40 + 32 + lane];
    }
}

// ---------------- launch ----------------
extern "C" void kernel_launch(void* const* d_in, const int* in_sizes, int n_in,
                              void* d_out, int out_size)
{
    const float* x      = (const float*)d_in[0];
    const float* qk_w   = (const float*)d_in[1];
    const float* proj_w = (const float*)d_in[2];
    const float* proj_b = (const float*)d_in[3];
    const float* we     = (const float*)d_in[4];
    const float* wr     = (const float*)d_in[5];
    const float* cw_w   = (const float*)d_in[6];
    const float* cw_b   = (const float*)d_in[7];
    float* out = (float*)d_out;

    float *xr, *qkwr, *qkn, *wc, *S, *Bg, *ob;
    cudaGetSymbolAddress((void**)&xr,   g_xr);
    cudaGetSymbolAddress((void**)&qkwr, g_qkwr);
    cudaGetSymbolAddress((void**)&qkn,  g_qkn);
    cudaGetSymbolAddress((void**)&wc,   g_wc);
    cudaGetSymbolAddress((void**)&S,    g_S);
    cudaGetSymbolAddress((void**)&Bg,   g_Bg);
    cudaGetSymbolAddress((void**)&ob,   g_obias);

    const int gemm_smem = 3 * STAGE_FLT * 4;                  // 98304
    cudaFuncSetAttribute(gemm_qk,
                         cudaFuncAttributeMaxDynamicSharedMemorySize, gemm_smem);
    cudaFuncSetAttribute(gemm_tf32,
                         cudaFuncAttributeMaxDynamicSharedMemorySize, gemm_smem);
    const int prep_smem = PR_TOT * 4;
    cudaFuncSetAttribute(prep_kernel,
                         cudaFuncAttributeMaxDynamicSharedMemorySize, prep_smem);
    const int sS_smem = (128 * 132 + 128 * 40) * 4;           // 88064
    cudaFuncSetAttribute(sgemm_S,
                         cudaFuncAttributeMaxDynamicSharedMemorySize, sS_smem);

    // independent prep work first
    {
        int total4 = MTOT * CH / 4 + QKW * CH / 4;
        round_all<<<(total4 + 255) / 256, 256>>>(x, qk_w, xr, qkwr);
    }
    prep_kernel<<<NBH, 256, prep_smem>>>(x, we, wr, wc);
    gprep_kernel<<<64, 256>>>(proj_w, cw_w, Bg);
    obias_kernel<<<CH / 8, 256>>>(proj_w, proj_b, cw_b, ob);

    // 1) qk gemm with fused normalize+transpose -> qkn
    {
        dim3 grid(QKW / 128, MTOT / 128);
        gemm_qk<<<grid, 256, gemm_smem>>>(xr, qkwr, qkn);
    }
    // 2) scores S = qkn^T @ wc
    {
        dim3 grid(SEQ / 128, NBH);
        sgemm_S<<<grid, 128, sS_smem>>>(qkn, wc, S);
    }
    // 3) out = S @ Bg^T + obias   (M=8192, Nn=1024, K=640)
    {
        dim3 grid(CH / 128, MTOT / 128);
        gemm_tf32<<<grid, 256, gemm_smem>>>(S, Bg, ob, out, CH, KS2);
    }
}

// round 9
// speedup vs baseline: 4.1883x; 1.1675x over previous
#include <cuda_runtime.h>
#include <cstdint>
#include <math.h>

// ---------------- problem constants ----------------
#define BCH 4
#define SEQ 2048
#define CH  1024
#define NH  16
#define HD  64
#define LR  20
#define RS  200
#define QKW (2*CH)
#define MTOT (BCH*SEQ)    // 8192
#define BK   32
#define STAGE_FLT (2*128*32)   // 32 KB per pipeline stage
#define NBH (BCH*NH)      // 64
#define KS2  640               // rank-structured K for the output gemm

// ---------------- scratch (device globals) ----------------
__device__ __align__(256) float g_xr[(size_t)MTOT * CH];
__device__ __align__(256) float g_qkwr[(size_t)QKW * CH];
__device__ __align__(256) float g_web[(size_t)NBH * HD * LR];   // [bh][d][j]
__device__ __align__(256) float g_wrb[(size_t)NBH * HD * LR];
__device__ __align__(256) float g_S[(size_t)MTOT * KS2];        // [b*n][h*40+j]
__device__ __align__(256) float g_Bg[(size_t)CH * KS2];         // [o][hj]
__device__ __align__(256) float g_obias[CH];

// ---------------- helpers ----------------
__device__ __forceinline__ float tf32r(float x) {
    float y;
    asm("cvt.rna.tf32.f32 %0, %1;" : "=f"(y) : "f"(x));
    return y;
}
__device__ __forceinline__ uint32_t smem_u32(const void* p) {
    uint32_t a;
    asm("{ .reg .u64 t; cvta.to.shared.u64 t, %1; cvt.u32.u64 %0, t; }"
        : "=r"(a) : "l"(p));
    return a;
}
#define CP_ASYNC16(dst, src) \
    asm volatile("cp.async.cg.shared.global [%0], [%1], 16;" :: "r"(dst), "l"(src))
#define CP_COMMIT() asm volatile("cp.async.commit_group;" ::: "memory")
#define CP_WAIT1()  asm volatile("cp.async.wait_group 1;" ::: "memory")

__device__ __forceinline__ void mma8(float* d, const float* a, const float* b) {
    asm volatile(
        "mma.sync.aligned.m16n8k8.row.col.f32.tf32.tf32.f32 "
        "{%0,%1,%2,%3}, {%4,%5,%6,%7}, {%8,%9}, {%0,%1,%2,%3};"
        : "+f"(d[0]), "+f"(d[1]), "+f"(d[2]), "+f"(d[3])
        : "r"(__float_as_uint(a[0])), "r"(__float_as_uint(a[1])),
          "r"(__float_as_uint(a[2])), "r"(__float_as_uint(a[3])),
          "r"(__float_as_uint(b[0])), "r"(__float_as_uint(b[1])));
}

// shared mainloop pieces -----------------------------------------------------
#define GEMM_PROLOG()                                                          \
    const int tid = threadIdx.x;                                               \
    const int wid = tid >> 5, lane = tid & 31;                                 \
    const int wm = wid >> 2;                                                   \
    const int wn = wid & 3;                                                    \
    const int gid = lane >> 2;                                                 \
    const int tig = lane & 3;                                                  \
    (void)lane;

#define COPY_STAGE(s, Kdim) do {                                               \
        const int _k0 = (s) * BK;                                              \
        const uint32_t _db = sbase + ((s) % 3) * (STAGE_FLT * 4);              \
        _Pragma("unroll")                                                      \
        for (int _i = 0; _i < 8; _i++) {                                       \
            int _id  = _i * 256 + tid;                                         \
            int _mat = _id >> 10;                                              \
            int _row = (_id >> 3) & 127;                                       \
            int _ch  = _id & 7;                                                \
            const float* _src = (_mat ? (B + (size_t)(n0 + _row) * (Kdim))     \
                                      : (A + (size_t)(m0 + _row) * (Kdim)))    \
                                + _k0 + _ch * 4;                               \
            uint32_t _dst = _db + (uint32_t)(_mat * 4096 + _row * 32 +         \
                                   ((_ch ^ (_row & 7)) << 2)) * 4u;            \
            CP_ASYNC16(_dst, _src);                                            \
        }                                                                      \
    } while (0)

#define GEMM_MAINLOOP(Kdim, nst)                                               \
    COPY_STAGE(0, Kdim); CP_COMMIT();                                          \
    COPY_STAGE(1, Kdim); CP_COMMIT();                                          \
    float acc[4][4][4];                                                        \
    _Pragma("unroll")                                                          \
    for (int mt = 0; mt < 4; mt++)                                             \
        _Pragma("unroll")                                                      \
        for (int nt = 0; nt < 4; nt++)                                         \
            _Pragma("unroll")                                                  \
            for (int r = 0; r < 4; r++) acc[mt][nt][r] = 0.f;                  \
    int mbase[4], nbase[4];                                                    \
    _Pragma("unroll")                                                          \
    for (int mt = 0; mt < 4; mt++)                                             \
        mbase[mt] = (wm * 64 + mt * 16 + gid) * 32 + tig;                      \
    _Pragma("unroll")                                                          \
    for (int nt = 0; nt < 4; nt++)                                             \
        nbase[nt] = (wn * 32 + nt * 8 + gid) * 32 + tig;                       \
    for (int c = 0; c < (nst); c++) {                                          \
        CP_WAIT1();                                                            \
        __syncthreads();                                                       \
        if (c + 2 < (nst)) COPY_STAGE(c + 2, Kdim);                            \
        CP_COMMIT();                                                           \
        const float* As = sm + (c % 3) * STAGE_FLT;                            \
        const float* Bs = As + 4096;                                           \
        _Pragma("unroll")                                                      \
        for (int ks = 0; ks < BK; ks += 8) {                                   \
            const int x0 = (((ks >> 2)     ) ^ gid) << 2;                      \
            const int x1 = (((ks >> 2) + 1) ^ gid) << 2;                       \
            float af[4][4], bf[4][2];                                          \
            _Pragma("unroll")                                                  \
            for (int mt = 0; mt < 4; mt++) {                                   \
                af[mt][0] = As[mbase[mt] + x0];                                \
                af[mt][1] = As[mbase[mt] + 256 + x0];                          \
                af[mt][2] = As[mbase[mt] + x1];                                \
                af[mt][3] = As[mbase[mt] + 256 + x1];                          \
            }                                                                  \
            _Pragma("unroll")                                                  \
            for (int nt = 0; nt < 4; nt++) {                                   \
                bf[nt][0] = Bs[nbase[nt] + x0];                                \
                bf[nt][1] = Bs[nbase[nt] + x1];                                \
            }                                                                  \
            _Pragma("unroll")                                                  \
            for (int mt = 0; mt < 4; mt++)                                     \
                _Pragma("unroll")                                              \
                for (int nt = 0; nt < 4; nt++)                                 \
                    mma8(acc[mt][nt], af[mt], bf[nt]);                         \
        }                                                                      \
    }

// ---------------- round pass (x and qk_w in one launch) ----------------
__global__ __launch_bounds__(256) void round_all(
    const float* __restrict__ x, const float* __restrict__ qkw,
    float* __restrict__ xr, float* __restrict__ qkwr)
{
    const int X4 = MTOT * CH / 4;
    const int W4 = QKW * CH / 4;
    int i = blockIdx.x * 256 + threadIdx.x;
    if (i < X4) {
        float4 v = ((const float4*)x)[i];
        v.x = tf32r(v.x); v.y = tf32r(v.y); v.z = tf32r(v.z); v.w = tf32r(v.w);
        ((float4*)xr)[i] = v;
    } else if (i < X4 + W4) {
        int j = i - X4;
        float4 v = ((const float4*)qkw)[j];
        v.x = tf32r(v.x); v.y = tf32r(v.y); v.z = tf32r(v.z); v.w = tf32r(v.w);
        ((float4*)qkwr)[j] = v;
    }
}

// ---------------- gemm_qk: qk tile -> norms -> scores S (fused) -------------
// Tile: rows = 128 sequence positions, cols = 2 complete heads of q (or k).
// Epilogue computes S[b,n,(h0+hh)*40 + joff + j] = (v . w[:,j]) / ||v||.
__global__ __launch_bounds__(256, 2) void gemm_qk(
    const float* __restrict__ A, const float* __restrict__ B,
    const float* __restrict__ web, const float* __restrict__ wrb,
    float* __restrict__ S)
{
    extern __shared__ float sm[];
    const uint32_t sbase = smem_u32(sm);
    GEMM_PROLOG();
    const int m0 = blockIdx.y * 128, n0 = blockIdx.x * 128;

    GEMM_MAINLOOP(CH, CH / BK);

    // ---- epilogue: transpose -> norms -> scores ----
    __syncthreads();
    float* st    = sm;                     // [128 col][132]
    float* snorm = sm + 128 * 132;         // [row][2]  (inverse norms)
    float* swb   = snorm + 256;            // [2 hh][64 d][20 j]
#pragma unroll
    for (int mt = 0; mt < 4; mt++)
#pragma unroll
        for (int half = 0; half < 2; half++) {
            int row = wm * 64 + mt * 16 + gid + half * 8;
#pragma unroll
            for (int nt = 0; nt < 4; nt++) {
                int col = wn * 32 + nt * 8 + tig * 2;
                st[(col)     * 132 + row] = acc[mt][nt][half * 2 + 0];
                st[(col + 1) * 132 + row] = acc[mt][nt][half * 2 + 1];
            }
        }

    const int b = (blockIdx.y * 128) >> 11;
    const int nseq0 = (blockIdx.y * 128) & 2047;
    const int c0 = blockIdx.x * 128;
    const int isK = (c0 >= 1024);
    const int h0 = isK ? ((c0 - 1024) >> 6) : (c0 >> 6);
    const int joff = isK ? LR : 0;
    const float* wsrc = isK ? wrb : web;

    // load per-head low-rank weights for the 2 heads of this tile
    for (int i = tid; i < 2 * HD * LR; i += 256) {
        int hh = i / (HD * LR), rem = i % (HD * LR);
        swb[i] = wsrc[(size_t)(b * NH + h0 + hh) * HD * LR + rem];
    }
    __syncthreads();

    // inverse norms
    {
        int r = tid & 127, hh = tid >> 7;
        float s = 0.f;
#pragma unroll 8
        for (int c = 0; c < 64; c++) {
            float v = st[(hh * 64 + c) * 132 + r];
            s += v * v;
        }
        snorm[r * 2 + hh] = 1.f / fmaxf(sqrtf(s), 1e-12f);
    }
    __syncthreads();

    // scores: warp handles 5 (hh,j) pairs; lane covers 4 n each
    float sacc[5][4];
    int php[5], pj[5];
#pragma unroll
    for (int pp = 0; pp < 5; pp++) {
        int p = wid * 5 + pp;
        php[pp] = p / LR;           // 0..1
        pj[pp]  = p % LR;           // 0..19
#pragma unroll
        for (int r = 0; r < 4; r++) sacc[pp][r] = 0.f;
    }
#pragma unroll 4
    for (int d = 0; d < HD; d++) {
#pragma unroll
        for (int pp = 0; pp < 5; pp++) {
            float wv = swb[php[pp] * HD * LR + d * LR + pj[pp]];
            const float* col = &st[(php[pp] * 64 + d) * 132];
#pragma unroll
            for (int r = 0; r < 4; r++)
                sacc[pp][r] += col[r * 32 + lane] * wv;
        }
    }
    __syncthreads();   // done reading st; reuse as sS[128 n][40]

    float* sS = sm;
#pragma unroll
    for (int pp = 0; pp < 5; pp++) {
#pragma unroll
        for (int r = 0; r < 4; r++) {
            int n = r * 32 + lane;
            sS[n * 40 + php[pp] * LR + pj[pp]] =
                tf32r(sacc[pp][r] * snorm[n * 2 + php[pp]]);
        }
    }
    __syncthreads();

    // store: warp per row; two 20-float segments (heads h0, h0+1)
    for (int it = 0; it < 16; it++) {
        int r = wid + 8 * it;
        float* dst = S + ((size_t)(b * SEQ + nseq0 + r)) * KS2 + joff;
        if (lane < LR) {
            dst[(h0)     * 40 + lane] = sS[r * 40 + lane];
            dst[(h0 + 1) * 40 + lane] = sS[r * 40 + LR + lane];
        }
    }
}

// ---------------- generic tf32 GEMM (runtime K) ----------------
__global__ __launch_bounds__(256, 2) void gemm_tf32(
    const float* __restrict__ A, const float* __restrict__ B,
    const float* __restrict__ bias, float* __restrict__ C,
    int Nn, int K)
{
    extern __shared__ float sm[];
    const uint32_t sbase = smem_u32(sm);
    GEMM_PROLOG();
    const int m0 = blockIdx.y * 128, n0 = blockIdx.x * 128;

    GEMM_MAINLOOP(K, K / BK);

    float bb[4][2];
#pragma unroll
    for (int nt = 0; nt < 4; nt++) {
        int col = n0 + wn * 32 + nt * 8 + tig * 2;
        bb[nt][0] = bias[col];
        bb[nt][1] = bias[col + 1];
    }
#pragma unroll
    for (int mt = 0; mt < 4; mt++)
#pragma unroll
        for (int half = 0; half < 2; half++) {
            int row = m0 + wm * 64 + mt * 16 + gid + half * 8;
            float* cp = C + (size_t)row * Nn + n0 + wn * 32 + tig * 2;
#pragma unroll
            for (int nt = 0; nt < 4; nt++) {
                float2 v;
                v.x = acc[mt][nt][half * 2 + 0] + bb[nt][0];
                v.y = acc[mt][nt][half * 2 + 1] + bb[nt][1];
                *(float2*)(cp + nt * 8) = v;
            }
        }
}

// ---------------- prep: gen_weights -> web/wrb [bh][d][j] ----------
#define PR_XH 0
#define PR_WE (PR_XH + RS*HD)
#define PR_WR (PR_WE + RS*LR)
#define PR_TOT (PR_WR + RS*LR)
__global__ __launch_bounds__(256) void prep_kernel(
    const float* __restrict__ x, const float* __restrict__ we,
    const float* __restrict__ wr, float* __restrict__ web,
    float* __restrict__ wrb)
{
    extern __shared__ float s[];
    const int bh = blockIdx.x;
    const int b = bh >> 4, h = bh & 15;
    const int tid = threadIdx.x;
    const double step = (double)(SEQ - 1) / (double)(RS - 1);

    for (int i = tid; i < RS * HD; i += 256) {
        int r = i >> 6, d = i & 63;
        int idx = (r == RS - 1) ? (SEQ - 1) : (int)((double)r * step);
        s[PR_XH + i] = x[((size_t)b * SEQ + idx) * CH + h * HD + d];
    }
    for (int i = tid; i < RS * LR; i += 256) {
        s[PR_WE + i] = we[h * RS * LR + i];
        s[PR_WR + i] = wr[h * RS * LR + i];
    }
    __syncthreads();

    for (int u = tid; u < 16 * LR; u += 256) {
        int d4 = (u & 15) * 4, e = u >> 4;
        float aE[4] = {0, 0, 0, 0}, aR[4] = {0, 0, 0, 0};
        for (int r = 0; r < RS; r++) {
            float4 xv = *(const float4*)&s[PR_XH + r * HD + d4];
            float wev = s[PR_WE + r * LR + e];
            float wrv = s[PR_WR + r * LR + e];
            aE[0] += xv.x * wev; aE[1] += xv.y * wev;
            aE[2] += xv.z * wev; aE[3] += xv.w * wev;
            aR[0] += xv.x * wrv; aR[1] += xv.y * wrv;
            aR[2] += xv.z * wrv; aR[3] += xv.w * wrv;
        }
        size_t base = (size_t)bh * HD * LR;
#pragma unroll
        for (int j = 0; j < 4; j++) {
            web[base + (d4 + j) * LR + e] = aE[j];
            wrb[base + (d4 + j) * LR + e] = aR[j];
        }
    }
}

// ---------------- gprep: Bg + obias in one kernel ----------------
// Bg[o][h*40+j] = sum_dp proj_w[o][h*64+dp]*cw_w[dp][j]
// obias[o] = proj_b[o] + sum_c cw_b[c%64]*proj_w[o][c]
__global__ __launch_bounds__(256) void gprep_kernel(
    const float* __restrict__ proj_w, const float* __restrict__ cw_w,
    const float* __restrict__ proj_b, const float* __restrict__ cw_b,
    float* __restrict__ Bg, float* __restrict__ obias)
{
    __shared__ float s_cw[HD * 40];
    __shared__ float s_cwb[HD];
    __shared__ float s_part[256];
    const int tid = threadIdx.x;
    for (int i = tid; i < HD * 40; i += 256) s_cw[i] = cw_w[i];
    if (tid < HD) s_cwb[tid] = cw_b[tid];
    __syncthreads();

    int idx = blockIdx.x * 256 + tid;
    int o = idx >> 4, h = idx & 15;
    float acc[40];
#pragma unroll
    for (int j = 0; j < 40; j++) acc[j] = 0.f;
    float part = 0.f;
    const float* pr = proj_w + (size_t)o * CH + h * HD;
    for (int dp = 0; dp < HD; dp++) {
        float pv = pr[dp];
        part += pv * s_cwb[dp];
#pragma unroll
        for (int j = 0; j < 40; j++) acc[j] += pv * s_cw[dp * 40 + j];
    }
    float* dst = Bg + (size_t)o * KS2 + h * 40;
#pragma unroll
    for (int j = 0; j < 40; j++) dst[j] = tf32r(acc[j]);

    s_part[tid] = part;
    __syncthreads();
    if (h == 0) {
        float t = proj_b[o];
#pragma unroll
        for (int i = 0; i < 16; i++) t += s_part[tid + i];
        obias[o] = t;
    }
}

// ---------------- launch ----------------
extern "C" void kernel_launch(void* const* d_in, const int* in_sizes, int n_in,
                              void* d_out, int out_size)
{
    const float* x      = (const float*)d_in[0];
    const float* qk_w   = (const float*)d_in[1];
    const float* proj_w = (const float*)d_in[2];
    const float* proj_b = (const float*)d_in[3];
    const float* we     = (const float*)d_in[4];
    const float* wr     = (const float*)d_in[5];
    const float* cw_w   = (const float*)d_in[6];
    const float* cw_b   = (const float*)d_in[7];
    float* out = (float*)d_out;

    float *xr, *qkwr, *web, *wrb, *S, *Bg, *ob;
    cudaGetSymbolAddress((void**)&xr,   g_xr);
    cudaGetSymbolAddress((void**)&qkwr, g_qkwr);
    cudaGetSymbolAddress((void**)&web,  g_web);
    cudaGetSymbolAddress((void**)&wrb,  g_wrb);
    cudaGetSymbolAddress((void**)&S,    g_S);
    cudaGetSymbolAddress((void**)&Bg,   g_Bg);
    cudaGetSymbolAddress((void**)&ob,   g_obias);

    const int gemm_smem = 3 * STAGE_FLT * 4;                  // 98304
    cudaFuncSetAttribute(gemm_qk,
                         cudaFuncAttributeMaxDynamicSharedMemorySize, gemm_smem);
    cudaFuncSetAttribute(gemm_tf32,
                         cudaFuncAttributeMaxDynamicSharedMemorySize, gemm_smem);
    const int prep_smem = PR_TOT * 4;
    cudaFuncSetAttribute(prep_kernel,
                         cudaFuncAttributeMaxDynamicSharedMemorySize, prep_smem);

    // independent prep work first
    {
        int total4 = MTOT * CH / 4 + QKW * CH / 4;
        round_all<<<(total4 + 255) / 256, 256>>>(x, qk_w, xr, qkwr);
    }
    prep_kernel<<<NBH, 256, prep_smem>>>(x, we, wr, web, wrb);
    gprep_kernel<<<64, 256>>>(proj_w, cw_w, proj_b, cw_b, Bg, ob);

    // 1) qk gemm fused with normalize + score computation -> S
    {
        dim3 grid(QKW / 128, MTOT / 128);
        gemm_qk<<<grid, 256, gemm_smem>>>(xr, qkwr, web, wrb, S);
    }
    // 2) out = S @ Bg^T + obias   (M=8192, Nn=1024, K=640)
    {
        dim3 grid(CH / 128, MTOT / 128);
        gemm_tf32<<<grid, 256, gemm_smem>>>(S, Bg, ob, out, CH, KS2);
    }
}

// round 11
// speedup vs baseline: 4.5803x; 1.0936x over previous
#include <cuda_runtime.h>
#include <cstdint>
#include <math.h>

// ---------------- problem constants ----------------
#define BCH 4
#define SEQ 2048
#define CH  1024
#define NH  16
#define HD  64
#define LR  20
#define RS  200
#define QKW (2*CH)
#define MTOT (BCH*SEQ)    // 8192
#define BK   32
#define STAGE_FLT (2*128*32)   // 32 KB per pipeline stage
#define NBH (BCH*NH)      // 64
#define KS2  640               // rank-structured K for the output gemm
#define NROUND 10240           // (MTOT*CH/4 + QKW*CH/4)/256

// ---------------- scratch (device globals) ----------------
__device__ __align__(256) float g_xr[(size_t)MTOT * CH];
__device__ __align__(256) float g_qkwr[(size_t)QKW * CH];
__device__ __align__(256) float g_webT[(size_t)NBH * LR * HD];  // [bh][j][d]
__device__ __align__(256) float g_wrbT[(size_t)NBH * LR * HD];
__device__ __align__(256) float g_S[(size_t)MTOT * KS2];        // [b*n][h*40+j]
__device__ __align__(256) float g_Bg[(size_t)CH * KS2];         // [o][hj]
__device__ __align__(256) float g_obias[CH];

// ---------------- helpers ----------------
__device__ __forceinline__ float tf32r(float x) {
    float y;
    asm("cvt.rna.tf32.f32 %0, %1;" : "=f"(y) : "f"(x));
    return y;
}
__device__ __forceinline__ uint32_t smem_u32(const void* p) {
    uint32_t a;
    asm("{ .reg .u64 t; cvta.to.shared.u64 t, %1; cvt.u32.u64 %0, t; }"
        : "=r"(a) : "l"(p));
    return a;
}
#define CP_ASYNC16(dst, src) \
    asm volatile("cp.async.cg.shared.global [%0], [%1], 16;" :: "r"(dst), "l"(src))
#define CP_COMMIT() asm volatile("cp.async.commit_group;" ::: "memory")
#define CP_WAIT1()  asm volatile("cp.async.wait_group 1;" ::: "memory")

__device__ __forceinline__ void mma8(float* d, const float* a, const float* b) {
    asm volatile(
        "mma.sync.aligned.m16n8k8.row.col.f32.tf32.tf32.f32 "
        "{%0,%1,%2,%3}, {%4,%5,%6,%7}, {%8,%9}, {%0,%1,%2,%3};"
        : "+f"(d[0]), "+f"(d[1]), "+f"(d[2]), "+f"(d[3])
        : "r"(__float_as_uint(a[0])), "r"(__float_as_uint(a[1])),
          "r"(__float_as_uint(a[2])), "r"(__float_as_uint(a[3])),
          "r"(__float_as_uint(b[0])), "r"(__float_as_uint(b[1])));
}

// shared mainloop pieces -----------------------------------------------------
#define GEMM_PROLOG()                                                          \
    const int tid = threadIdx.x;                                               \
    const int wid = tid >> 5, lane = tid & 31;                                 \
    const int wm = wid >> 2;                                                   \
    const int wn = wid & 3;                                                    \
    const int gid = lane >> 2;                                                 \
    const int tig = lane & 3;                                                  \
    (void)lane;

#define COPY_STAGE(s, Kdim) do {                                               \
        const int _k0 = (s) * BK;                                              \
        const uint32_t _db = sbase + ((s) % 3) * (STAGE_FLT * 4);              \
        _Pragma("unroll")                                                      \
        for (int _i = 0; _i < 8; _i++) {                                       \
            int _id  = _i * 256 + tid;                                         \
            int _mat = _id >> 10;                                              \
            int _row = (_id >> 3) & 127;                                       \
            int _ch  = _id & 7;                                                \
            const float* _src = (_mat ? (B + (size_t)(n0 + _row) * (Kdim))     \
                                      : (A + (size_t)(m0 + _row) * (Kdim)))    \
                                + _k0 + _ch * 4;                               \
            uint32_t _dst = _db + (uint32_t)(_mat * 4096 + _row * 32 +         \
                                   ((_ch ^ (_row & 7)) << 2)) * 4u;            \
            CP_ASYNC16(_dst, _src);                                            \
        }                                                                      \
    } while (0)

#define GEMM_MAINLOOP(Kdim, nst)                                               \
    COPY_STAGE(0, Kdim); CP_COMMIT();                                          \
    COPY_STAGE(1, Kdim); CP_COMMIT();                                          \
    float acc[4][4][4];                                                        \
    _Pragma("unroll")                                                          \
    for (int mt = 0; mt < 4; mt++)                                             \
        _Pragma("unroll")                                                      \
        for (int nt = 0; nt < 4; nt++)                                         \
            _Pragma("unroll")                                                  \
            for (int r = 0; r < 4; r++) acc[mt][nt][r] = 0.f;                  \
    int mbase[4], nbase[4];                                                    \
    _Pragma("unroll")                                                          \
    for (int mt = 0; mt < 4; mt++)                                             \
        mbase[mt] = (wm * 64 + mt * 16 + gid) * 32 + tig;                      \
    _Pragma("unroll")                                                          \
    for (int nt = 0; nt < 4; nt++)                                             \
        nbase[nt] = (wn * 32 + nt * 8 + gid) * 32 + tig;                       \
    for (int c = 0; c < (nst); c++) {                                          \
        CP_WAIT1();                                                            \
        __syncthreads();                                                       \
        if (c + 2 < (nst)) COPY_STAGE(c + 2, Kdim);                            \
        CP_COMMIT();                                                           \
        const float* As = sm + (c % 3) * STAGE_FLT;                            \
        const float* Bs = As + 4096;                                           \
        _Pragma("unroll")                                                      \
        for (int ks = 0; ks < BK; ks += 8) {                                   \
            const int x0 = (((ks >> 2)     ) ^ gid) << 2;                      \
            const int x1 = (((ks >> 2) + 1) ^ gid) << 2;                       \
            float af[4][4], bf[4][2];                                          \
            _Pragma("unroll")                                                  \
            for (int mt = 0; mt < 4; mt++) {                                   \
                af[mt][0] = As[mbase[mt] + x0];                                \
                af[mt][1] = As[mbase[mt] + 256 + x0];                          \
                af[mt][2] = As[mbase[mt] + x1];                                \
                af[mt][3] = As[mbase[mt] + 256 + x1];                          \
            }                                                                  \
            _Pragma("unroll")                                                  \
            for (int nt = 0; nt < 4; nt++) {                                   \
                bf[nt][0] = Bs[nbase[nt] + x0];                                \
                bf[nt][1] = Bs[nbase[nt] + x1];                                \
            }                                                                  \
            _Pragma("unroll")                                                  \
            for (int mt = 0; mt < 4; mt++)                                     \
                _Pragma("unroll")                                              \
                for (int nt = 0; nt < 4; nt++)                                 \
                    mma8(acc[mt][nt], af[mt], bf[nt]);                         \
        }                                                                      \
    }

// ---------------- fused setup: round x/qk_w + prep(webT/wrbT) + gprep -------
#define PR_XH 0
#define PR_WE (PR_XH + RS*HD)
#define PR_WR (PR_WE + RS*LR)
#define PR_TOT (PR_WR + RS*LR)   // 20800 floats
__global__ __launch_bounds__(256) void setup_kernel(
    const float* __restrict__ x, const float* __restrict__ qkw,
    const float* __restrict__ we, const float* __restrict__ wr,
    const float* __restrict__ proj_w, const float* __restrict__ cw_w,
    const float* __restrict__ proj_b, const float* __restrict__ cw_b,
    float* __restrict__ xr, float* __restrict__ qkwr,
    float* __restrict__ webT, float* __restrict__ wrbT,
    float* __restrict__ Bg, float* __restrict__ obias)
{
    extern __shared__ float s[];
    const int tid = threadIdx.x;
    const int bid = blockIdx.x;

    if (bid < NROUND) {
        // ---- tf32 rounding of x and qk_w ----
        const int X4 = MTOT * CH / 4;
        int i = bid * 256 + tid;
        if (i < X4) {
            float4 v = ((const float4*)x)[i];
            v.x = tf32r(v.x); v.y = tf32r(v.y);
            v.z = tf32r(v.z); v.w = tf32r(v.w);
            ((float4*)xr)[i] = v;
        } else {
            int j = i - X4;
            float4 v = ((const float4*)qkw)[j];
            v.x = tf32r(v.x); v.y = tf32r(v.y);
            v.z = tf32r(v.z); v.w = tf32r(v.w);
            ((float4*)qkwr)[j] = v;
        }
        return;
    }
    if (bid < NROUND + NBH) {
        // ---- prep: gen_weights -> webT/wrbT [bh][j][d], tf32-rounded ----
        const int bh = bid - NROUND;
        const int b = bh >> 4, h = bh & 15;
        const double step = (double)(SEQ - 1) / (double)(RS - 1);

        for (int i = tid; i < RS * HD; i += 256) {
            int r = i >> 6, d = i & 63;
            int idx = (r == RS - 1) ? (SEQ - 1) : (int)((double)r * step);
            s[PR_XH + i] = x[((size_t)b * SEQ + idx) * CH + h * HD + d];
        }
        for (int i = tid; i < RS * LR; i += 256) {
            s[PR_WE + i] = we[h * RS * LR + i];
            s[PR_WR + i] = wr[h * RS * LR + i];
        }
        __syncthreads();

        for (int u = tid; u < 16 * LR; u += 256) {
            int d4 = (u & 15) * 4, e = u >> 4;
            float aE[4] = {0, 0, 0, 0}, aR[4] = {0, 0, 0, 0};
            for (int r = 0; r < RS; r++) {
                float4 xv = *(const float4*)&s[PR_XH + r * HD + d4];
                float wev = s[PR_WE + r * LR + e];
                float wrv = s[PR_WR + r * LR + e];
                aE[0] += xv.x * wev; aE[1] += xv.y * wev;
                aE[2] += xv.z * wev; aE[3] += xv.w * wev;
                aR[0] += xv.x * wrv; aR[1] += xv.y * wrv;
                aR[2] += xv.z * wrv; aR[3] += xv.w * wrv;
            }
            size_t base = (size_t)bh * LR * HD + (size_t)e * HD;
#pragma unroll
            for (int j = 0; j < 4; j++) {
                webT[base + d4 + j] = tf32r(aE[j]);
                wrbT[base + d4 + j] = tf32r(aR[j]);
            }
        }
        return;
    }
    // ---- gprep: Bg + obias ----
    {
        float* s_cw  = s;             // 64*40
        float* s_cwb = s + HD * 40;   // 64
        float* s_part = s_cwb + HD;   // 256
        for (int i = tid; i < HD * 40; i += 256) s_cw[i] = cw_w[i];
        if (tid < HD) s_cwb[tid] = cw_b[tid];
        __syncthreads();

        int idx = (bid - NROUND - NBH) * 256 + tid;
        int o = idx >> 4, h = idx & 15;
        float acc[40];
#pragma unroll
        for (int j = 0; j < 40; j++) acc[j] = 0.f;
        float part = 0.f;
        const float* pr = proj_w + (size_t)o * CH + h * HD;
        for (int dp = 0; dp < HD; dp++) {
            float pv = pr[dp];
            part += pv * s_cwb[dp];
#pragma unroll
            for (int j = 0; j < 40; j++) acc[j] += pv * s_cw[dp * 40 + j];
        }
        float* dst = Bg + (size_t)o * KS2 + h * 40;
#pragma unroll
        for (int j = 0; j < 40; j++) dst[j] = tf32r(acc[j]);

        s_part[tid] = part;
        __syncthreads();
        if (h == 0) {
            float t = proj_b[o];
#pragma unroll
            for (int i = 0; i < 16; i++) t += s_part[tid + i];
            obias[o] = t;
        }
    }
}

// ---------------- gemm_qk: qk tile -> norms -> scores via tensor MMA --------
// smem epilogue layout: sv[128][132], snorm[256], Ws[40][132]
#define EP_SV   0
#define EP_NORM (128*132)
#define EP_WS   (EP_NORM + 256)
__global__ __launch_bounds__(256, 2) void gemm_qk(
    const float* __restrict__ A, const float* __restrict__ B,
    const float* __restrict__ webT, const float* __restrict__ wrbT,
    float* __restrict__ S)
{
    extern __shared__ float sm[];
    const uint32_t sbase = smem_u32(sm);
    GEMM_PROLOG();
    const int m0 = blockIdx.y * 128, n0 = blockIdx.x * 128;

    GEMM_MAINLOOP(CH, CH / BK);

    __syncthreads();

    const int b = m0 >> 11;
    const int nseq0 = m0 & 2047;
    const int c0 = blockIdx.x * 128;
    const int isK = (c0 >= 1024);
    const int h0 = isK ? ((c0 - 1024) >> 6) : (c0 >> 6);
    const int joff = isK ? LR : 0;
    const float* wsrc = isK ? wrbT : webT;

    float* sv    = sm + EP_SV;
    float* snorm = sm + EP_NORM;
    float* Ws    = sm + EP_WS;

    // (a) STS acc -> sv[n][d], tf32-rounded
#pragma unroll
    for (int mt = 0; mt < 4; mt++)
#pragma unroll
        for (int half = 0; half < 2; half++) {
            int row = wm * 64 + mt * 16 + gid + half * 8;
#pragma unroll
            for (int nt = 0; nt < 4; nt++) {
                float2 v;
                v.x = tf32r(acc[mt][nt][half * 2 + 0]);
                v.y = tf32r(acc[mt][nt][half * 2 + 1]);
                *(float2*)(sv + row * 132 + wn * 32 + nt * 8 + tig * 2) = v;
            }
        }

    // (b) stage Wpad[40][132] in one race-free pass (zero outside head range)
    for (int i = tid; i < 40 * 132; i += 256) {
        int j40 = i / 132, c = i % 132;
        int hh = (j40 >= LR);
        int jj = j40 - hh * LR;
        float v = 0.f;
        if (c < 128 && (c >> 6) == hh)
            v = wsrc[(size_t)(b * NH + h0 + hh) * LR * HD + jj * HD + (c & 63)];
        Ws[i] = v;
    }
    __syncthreads();

    // (c) inverse norms: thread (r, hh) reads contiguous 64 floats
    {
        int r = tid & 127, hh = tid >> 7;
        const float4* vp = (const float4*)(sv + r * 132 + hh * 64);
        float ssum = 0.f;
#pragma unroll
        for (int i = 0; i < 16; i++) {
            float4 v = vp[i];
            ssum += v.x * v.x + v.y * v.y + v.z * v.z + v.w * v.w;
        }
        snorm[r * 2 + hh] = 1.f / fmaxf(sqrtf(ssum), 1e-12f);
    }

    // (d) scores via mma: warp slab = 16 rows, R[16][40] over K=128
    float racc[5][4];
#pragma unroll
    for (int jt = 0; jt < 5; jt++)
#pragma unroll
        for (int r = 0; r < 4; r++) racc[jt][r] = 0.f;
    {
        const int ar0 = (wid * 16 + gid) * 132;
        const int ar1 = ar0 + 8 * 132;
#pragma unroll
        for (int ks = 0; ks < 128; ks += 8) {
            float af[4];
            af[0] = sv[ar0 + ks + tig];
            af[1] = sv[ar1 + ks + tig];
            af[2] = sv[ar0 + ks + 4 + tig];
            af[3] = sv[ar1 + ks + 4 + tig];
#pragma unroll
            for (int jt = 0; jt < 5; jt++) {
                float bf[2];
                bf[0] = Ws[(jt * 8 + gid) * 132 + ks + tig];
                bf[1] = Ws[(jt * 8 + gid) * 132 + ks + 4 + tig];
                mma8(racc[jt], af, bf);
            }
        }
    }
    __syncthreads();   // all reads of sv done; reuse as sS[128][40]

    // (e) scale by inverse norm, stage sS
    float* sS = sm;
    {
        int r1 = wid * 16 + gid, r2 = r1 + 8;
#pragma unroll
        for (int jt = 0; jt < 5; jt++) {
            int j0 = jt * 8 + tig * 2;
            int hh = (j0 >= LR);
            float n1 = snorm[r1 * 2 + hh], n2 = snorm[r2 * 2 + hh];
            sS[r1 * 40 + j0]     = tf32r(racc[jt][0] * n1);
            sS[r1 * 40 + j0 + 1] = tf32r(racc[jt][1] * n1);
            sS[r2 * 40 + j0]     = tf32r(racc[jt][2] * n2);
            sS[r2 * 40 + j0 + 1] = tf32r(racc[jt][3] * n2);
        }
    }
    __syncthreads();

    // (f) coalesced store to S
    for (int it = 0; it < 16; it++) {
        int r = wid + 8 * it;
        float* dst = S + ((size_t)(b * SEQ + nseq0 + r)) * KS2 + joff;
        if (lane < LR) {
            dst[(h0)     * 40 + lane] = sS[r * 40 + lane];
            dst[(h0 + 1) * 40 + lane] = sS[r * 40 + LR + lane];
        }
    }
}

// ---------------- generic tf32 GEMM (runtime K) ----------------
__global__ __launch_bounds__(256, 2) void gemm_tf32(
    const float* __restrict__ A, const float* __restrict__ B,
    const float* __restrict__ bias, float* __restrict__ C,
    int Nn, int K)
{
    extern __shared__ float sm[];
    const uint32_t sbase = smem_u32(sm);
    GEMM_PROLOG();
    const int m0 = blockIdx.y * 128, n0 = blockIdx.x * 128;

    GEMM_MAINLOOP(K, K / BK);

    float bb[4][2];
#pragma unroll
    for (int nt = 0; nt < 4; nt++) {
        int col = n0 + wn * 32 + nt * 8 + tig * 2;
        bb[nt][0] = bias[col];
        bb[nt][1] = bias[col + 1];
    }
#pragma unroll
    for (int mt = 0; mt < 4; mt++)
#pragma unroll
        for (int half = 0; half < 2; half++) {
            int row = m0 + wm * 64 + mt * 16 + gid + half * 8;
            float* cp = C + (size_t)row * Nn + n0 + wn * 32 + tig * 2;
#pragma unroll
            for (int nt = 0; nt < 4; nt++) {
                float2 v;
                v.x = acc[mt][nt][half * 2 + 0] + bb[nt][0];
                v.y = acc[mt][nt][half * 2 + 1] + bb[nt][1];
                *(float2*)(cp + nt * 8) = v;
            }
        }
}

// ---------------- launch ----------------
extern "C" void kernel_launch(void* const* d_in, const int* in_sizes, int n_in,
                              void* d_out, int out_size)
{
    const float* x      = (const float*)d_in[0];
    const float* qk_w   = (const float*)d_in[1];
    const float* proj_w = (const float*)d_in[2];
    const float* proj_b = (const float*)d_in[3];
    const float* we     = (const float*)d_in[4];
    const float* wr     = (const float*)d_in[5];
    const float* cw_w   = (const float*)d_in[6];
    const float* cw_b   = (const float*)d_in[7];
    float* out = (float*)d_out;

    float *xr, *qkwr, *webT, *wrbT, *S, *Bg, *ob;
    cudaGetSymbolAddress((void**)&xr,   g_xr);
    cudaGetSymbolAddress((void**)&qkwr, g_qkwr);
    cudaGetSymbolAddress((void**)&webT, g_webT);
    cudaGetSymbolAddress((void**)&wrbT, g_wrbT);
    cudaGetSymbolAddress((void**)&S,    g_S);
    cudaGetSymbolAddress((void**)&Bg,   g_Bg);
    cudaGetSymbolAddress((void**)&ob,   g_obias);

    const int gemm_smem = 3 * STAGE_FLT * 4;                  // 98304
    cudaFuncSetAttribute(gemm_qk,
                         cudaFuncAttributeMaxDynamicSharedMemorySize, gemm_smem);
    cudaFuncSetAttribute(gemm_tf32,
                         cudaFuncAttributeMaxDynamicSharedMemorySize, gemm_smem);
    const int setup_smem = PR_TOT * 4;                        // 83200
    cudaFuncSetAttribute(setup_kernel,
                         cudaFuncAttributeMaxDynamicSharedMemorySize, setup_smem);

    // fused: round x/qk_w + prep + gprep (all independent)
    setup_kernel<<<NROUND + NBH + 64, 256, setup_smem>>>(
        x, qk_w, we, wr, proj_w, cw_w, proj_b, cw_b,
        xr, qkwr, webT, wrbT, Bg, ob);

    // 1) qk gemm fused with normalize + tensor-core score epilogue -> S
    {
        dim3 grid(QKW / 128, MTOT / 128);
        gemm_qk<<<grid, 256, gemm_smem>>>(xr, qkwr, webT, wrbT, S);
    }
    // 2) out = S @ Bg^T + obias   (M=8192, Nn=1024, K=640)
    {
        dim3 grid(CH / 128, MTOT / 128);
        gemm_tf32<<<grid, 256, gemm_smem>>>(S, Bg, ob, out, CH, KS2);
    }
}

// round 12
// speedup vs baseline: 5.0140x; 1.0947x over previous
#include <cuda_runtime.h>
#include <cstdint>
#include <math.h>

// ---------------- problem constants ----------------
#define BCH 4
#define SEQ 2048
#define CH  1024
#define NH  16
#define HD  64
#define LR  20
#define RS  200
#define QKW (2*CH)
#define MTOT (BCH*SEQ)    // 8192
#define BK   32
#define STAGE_FLT (2*128*32)   // 32 KB per pipeline stage
#define NBH (BCH*NH)      // 64
#define KS2  640               // rank-structured K for the output gemm

// ---------------- scratch (device globals) ----------------
__device__ __align__(256) float g_xr[(size_t)MTOT * CH];
__device__ __align__(256) float g_qkwr[(size_t)QKW * CH];
__device__ __align__(256) float g_webT[(size_t)NBH * LR * HD];  // [bh][j][d]
__device__ __align__(256) float g_wrbT[(size_t)NBH * LR * HD];
__device__ __align__(256) float g_S[(size_t)MTOT * KS2];        // [b*n][h*40+j]
__device__ __align__(256) float g_Bg[(size_t)CH * KS2];         // [o][hj]
__device__ __align__(256) float g_obias[CH];

// ---------------- helpers ----------------
__device__ __forceinline__ float tf32r(float x) {
    float y;
    asm("cvt.rna.tf32.f32 %0, %1;" : "=f"(y) : "f"(x));
    return y;
}
__device__ __forceinline__ uint32_t smem_u32(const void* p) {
    uint32_t a;
    asm("{ .reg .u64 t; cvta.to.shared.u64 t, %1; cvt.u32.u64 %0, t; }"
        : "=r"(a) : "l"(p));
    return a;
}
#define CP_ASYNC16(dst, src) \
    asm volatile("cp.async.cg.shared.global [%0], [%1], 16;" :: "r"(dst), "l"(src))
#define CP_COMMIT() asm volatile("cp.async.commit_group;" ::: "memory")
#define CP_WAIT1()  asm volatile("cp.async.wait_group 1;" ::: "memory")

__device__ __forceinline__ void mma8(float* d, const float* a, const float* b) {
    asm volatile(
        "mma.sync.aligned.m16n8k8.row.col.f32.tf32.tf32.f32 "
        "{%0,%1,%2,%3}, {%4,%5,%6,%7}, {%8,%9}, {%0,%1,%2,%3};"
        : "+f"(d[0]), "+f"(d[1]), "+f"(d[2]), "+f"(d[3])
        : "r"(__float_as_uint(a[0])), "r"(__float_as_uint(a[1])),
          "r"(__float_as_uint(a[2])), "r"(__float_as_uint(a[3])),
          "r"(__float_as_uint(b[0])), "r"(__float_as_uint(b[1])));
}

// shared mainloop pieces -----------------------------------------------------
#define GEMM_PROLOG()                                                          \
    const int tid = threadIdx.x;                                               \
    const int wid = tid >> 5, lane = tid & 31;                                 \
    const int wm = wid >> 2;                                                   \
    const int wn = wid & 3;                                                    \
    const int gid = lane >> 2;                                                 \
    const int tig = lane & 3;                                                  \
    (void)lane;

#define COPY_STAGE(s, Kdim) do {                                               \
        const int _k0 = (s) * BK;                                              \
        const uint32_t _db = sbase + ((s) % 3) * (STAGE_FLT * 4);              \
        _Pragma("unroll")                                                      \
        for (int _i = 0; _i < 8; _i++) {                                       \
            int _id  = _i * 256 + tid;                                         \
            int _mat = _id >> 10;                                              \
            int _row = (_id >> 3) & 127;                                       \
            int _ch  = _id & 7;                                                \
            const float* _src = (_mat ? (B + (size_t)(n0 + _row) * (Kdim))     \
                                      : (A + (size_t)(m0 + _row) * (Kdim)))    \
                                + _k0 + _ch * 4;                               \
            uint32_t _dst = _db + (uint32_t)(_mat * 4096 + _row * 32 +         \
                                   ((_ch ^ (_row & 7)) << 2)) * 4u;            \
            CP_ASYNC16(_dst, _src);                                            \
        }                                                                      \
    } while (0)

#define GEMM_MAINLOOP(Kdim, nst)                                               \
    COPY_STAGE(0, Kdim); CP_COMMIT();                                          \
    COPY_STAGE(1, Kdim); CP_COMMIT();                                          \
    float acc[4][4][4];                                                        \
    _Pragma("unroll")                                                          \
    for (int mt = 0; mt < 4; mt++)                                             \
        _Pragma("unroll")                                                      \
        for (int nt = 0; nt < 4; nt++)                                         \
            _Pragma("unroll")                                                  \
            for (int r = 0; r < 4; r++) acc[mt][nt][r] = 0.f;                  \
    int mbase[4], nbase[4];                                                    \
    _Pragma("unroll")                                                          \
    for (int mt = 0; mt < 4; mt++)                                             \
        mbase[mt] = (wm * 64 + mt * 16 + gid) * 32 + tig;                      \
    _Pragma("unroll")                                                          \
    for (int nt = 0; nt < 4; nt++)                                             \
        nbase[nt] = (wn * 32 + nt * 8 + gid) * 32 + tig;                       \
    for (int c = 0; c < (nst); c++) {                                          \
        CP_WAIT1();                                                            \
        __syncthreads();                                                       \
        if (c + 2 < (nst)) COPY_STAGE(c + 2, Kdim);                            \
        CP_COMMIT();                                                           \
        const float* As = sm + (c % 3) * STAGE_FLT;                            \
        const float* Bs = As + 4096;                                           \
        _Pragma("unroll")                                                      \
        for (int ks = 0; ks < BK; ks += 8) {                                   \
            const int x0 = (((ks >> 2)     ) ^ gid) << 2;                      \
            const int x1 = (((ks >> 2) + 1) ^ gid) << 2;                       \
            float af[4][4], bf[4][2];                                          \
            _Pragma("unroll")                                                  \
            for (int mt = 0; mt < 4; mt++) {                                   \
                af[mt][0] = As[mbase[mt] + x0];                                \
                af[mt][1] = As[mbase[mt] + 256 + x0];                          \
                af[mt][2] = As[mbase[mt] + x1];                                \
                af[mt][3] = As[mbase[mt] + 256 + x1];                          \
            }                                                                  \
            _Pragma("unroll")                                                  \
            for (int nt = 0; nt < 4; nt++) {                                   \
                bf[nt][0] = Bs[nbase[nt] + x0];                                \
                bf[nt][1] = Bs[nbase[nt] + x1];                                \
            }                                                                  \
            _Pragma("unroll")                                                  \
            for (int mt = 0; mt < 4; mt++)                                     \
                _Pragma("unroll")                                              \
                for (int nt = 0; nt < 4; nt++)                                 \
                    mma8(acc[mt][nt], af[mt], bf[nt]);                         \
        }                                                                      \
    }

// ---------------- round pass: x and qk_w -> tf32 grid (no smem) ------------
__global__ __launch_bounds__(256) void round_kernel(
    const float* __restrict__ x, const float* __restrict__ qkw,
    float* __restrict__ xr, float* __restrict__ qkwr)
{
    const int X4 = MTOT * CH / 4;
    const int T4 = X4 + QKW * CH / 4;
    for (int i = blockIdx.x * 256 + threadIdx.x; i < T4;
         i += gridDim.x * 256) {
        if (i < X4) {
            float4 v = ((const float4*)x)[i];
            v.x = tf32r(v.x); v.y = tf32r(v.y);
            v.z = tf32r(v.z); v.w = tf32r(v.w);
            ((float4*)xr)[i] = v;
        } else {
            int j = i - X4;
            float4 v = ((const float4*)qkw)[j];
            v.x = tf32r(v.x); v.y = tf32r(v.y);
            v.z = tf32r(v.z); v.w = tf32r(v.w);
            ((float4*)qkwr)[j] = v;
        }
    }
}

// ---------------- prep: gen_weights (blocks 0..63) + gprep (64..127) --------
#define PR_XH 0
#define PR_WE (PR_XH + RS*HD)
#define PR_WR (PR_WE + RS*LR)
#define PR_TOT (PR_WR + RS*LR)   // 20800 floats
__global__ __launch_bounds__(256) void prep_kernel(
    const float* __restrict__ x,
    const float* __restrict__ we, const float* __restrict__ wr,
    const float* __restrict__ proj_w, const float* __restrict__ cw_w,
    const float* __restrict__ proj_b, const float* __restrict__ cw_b,
    float* __restrict__ webT, float* __restrict__ wrbT,
    float* __restrict__ Bg, float* __restrict__ obias)
{
    extern __shared__ float s[];
    const int tid = threadIdx.x;
    const int bid = blockIdx.x;

    if (bid < NBH) {
        // ---- gen_weights -> webT/wrbT [bh][j][d], tf32-rounded ----
        const int bh = bid;
        const int b = bh >> 4, h = bh & 15;
        const double step = (double)(SEQ - 1) / (double)(RS - 1);

        for (int i = tid; i < RS * HD; i += 256) {
            int r = i >> 6, d = i & 63;
            int idx = (r == RS - 1) ? (SEQ - 1) : (int)((double)r * step);
            s[PR_XH + i] = x[((size_t)b * SEQ + idx) * CH + h * HD + d];
        }
        for (int i = tid; i < RS * LR; i += 256) {
            s[PR_WE + i] = we[h * RS * LR + i];
            s[PR_WR + i] = wr[h * RS * LR + i];
        }
        __syncthreads();

        for (int u = tid; u < 16 * LR; u += 256) {
            int d4 = (u & 15) * 4, e = u >> 4;
            float aE[4] = {0, 0, 0, 0}, aR[4] = {0, 0, 0, 0};
            for (int r = 0; r < RS; r++) {
                float4 xv = *(const float4*)&s[PR_XH + r * HD + d4];
                float wev = s[PR_WE + r * LR + e];
                float wrv = s[PR_WR + r * LR + e];
                aE[0] += xv.x * wev; aE[1] += xv.y * wev;
                aE[2] += xv.z * wev; aE[3] += xv.w * wev;
                aR[0] += xv.x * wrv; aR[1] += xv.y * wrv;
                aR[2] += xv.z * wrv; aR[3] += xv.w * wrv;
            }
            size_t base = (size_t)bh * LR * HD + (size_t)e * HD;
#pragma unroll
            for (int j = 0; j < 4; j++) {
                webT[base + d4 + j] = tf32r(aE[j]);
                wrbT[base + d4 + j] = tf32r(aR[j]);
            }
        }
        return;
    }
    // ---- gprep: Bg + obias ----
    {
        float* s_cw  = s;             // 64*40
        float* s_cwb = s + HD * 40;   // 64
        float* s_part = s_cwb + HD;   // 256
        for (int i = tid; i < HD * 40; i += 256) s_cw[i] = cw_w[i];
        if (tid < HD) s_cwb[tid] = cw_b[tid];
        __syncthreads();

        int idx = (bid - NBH) * 256 + tid;
        int o = idx >> 4, h = idx & 15;
        float acc[40];
#pragma unroll
        for (int j = 0; j < 40; j++) acc[j] = 0.f;
        float part = 0.f;
        const float* pr = proj_w + (size_t)o * CH + h * HD;
        for (int dp = 0; dp < HD; dp++) {
            float pv = pr[dp];
            part += pv * s_cwb[dp];
#pragma unroll
            for (int j = 0; j < 40; j++) acc[j] += pv * s_cw[dp * 40 + j];
        }
        float* dst = Bg + (size_t)o * KS2 + h * 40;
#pragma unroll
        for (int j = 0; j < 40; j++) dst[j] = tf32r(acc[j]);

        s_part[tid] = part;
        __syncthreads();
        if (h == 0) {
            float t = proj_b[o];
#pragma unroll
            for (int i = 0; i < 16; i++) t += s_part[tid + i];
            obias[o] = t;
        }
    }
}

// ---------------- gemm_qk: qk tile -> norms -> scores via tensor MMA --------
// smem epilogue layout: sv[128][132], snorm[256], Ws[40][132]
#define EP_SV   0
#define EP_NORM (128*132)
#define EP_WS   (EP_NORM + 256)
__global__ __launch_bounds__(256, 2) void gemm_qk(
    const float* __restrict__ A, const float* __restrict__ B,
    const float* __restrict__ webT, const float* __restrict__ wrbT,
    float* __restrict__ S)
{
    extern __shared__ float sm[];
    const uint32_t sbase = smem_u32(sm);
    GEMM_PROLOG();
    const int m0 = blockIdx.y * 128, n0 = blockIdx.x * 128;

    GEMM_MAINLOOP(CH, CH / BK);

    __syncthreads();

    const int b = m0 >> 11;
    const int nseq0 = m0 & 2047;
    const int c0 = blockIdx.x * 128;
    const int isK = (c0 >= 1024);
    const int h0 = isK ? ((c0 - 1024) >> 6) : (c0 >> 6);
    const int joff = isK ? LR : 0;
    const float* wsrc = isK ? wrbT : webT;

    float* sv    = sm + EP_SV;
    float* snorm = sm + EP_NORM;
    float* Ws    = sm + EP_WS;

    // (a) STS acc -> sv[n][d], tf32-rounded
#pragma unroll
    for (int mt = 0; mt < 4; mt++)
#pragma unroll
        for (int half = 0; half < 2; half++) {
            int row = wm * 64 + mt * 16 + gid + half * 8;
#pragma unroll
            for (int nt = 0; nt < 4; nt++) {
                float2 v;
                v.x = tf32r(acc[mt][nt][half * 2 + 0]);
                v.y = tf32r(acc[mt][nt][half * 2 + 1]);
                *(float2*)(sv + row * 132 + wn * 32 + nt * 8 + tig * 2) = v;
            }
        }

    // (b) stage Wpad[40][132] in one race-free pass (zero outside head range)
    for (int i = tid; i < 40 * 132; i += 256) {
        int j40 = i / 132, c = i % 132;
        int hh = (j40 >= LR);
        int jj = j40 - hh * LR;
        float v = 0.f;
        if (c < 128 && (c >> 6) == hh)
            v = wsrc[(size_t)(b * NH + h0 + hh) * LR * HD + jj * HD + (c & 63)];
        Ws[i] = v;
    }
    __syncthreads();

    // (c) inverse norms: thread (r, hh) reads contiguous 64 floats
    {
        int r = tid & 127, hh = tid >> 7;
        const float4* vp = (const float4*)(sv + r * 132 + hh * 64);
        float ssum = 0.f;
#pragma unroll
        for (int i = 0; i < 16; i++) {
            float4 v = vp[i];
            ssum += v.x * v.x + v.y * v.y + v.z * v.z + v.w * v.w;
        }
        snorm[r * 2 + hh] = 1.f / fmaxf(sqrtf(ssum), 1e-12f);
    }

    // (d) scores via mma: warp slab = 16 rows, R[16][40] over K=128
    float racc[5][4];
#pragma unroll
    for (int jt = 0; jt < 5; jt++)
#pragma unroll
        for (int r = 0; r < 4; r++) racc[jt][r] = 0.f;
    {
        const int ar0 = (wid * 16 + gid) * 132;
        const int ar1 = ar0 + 8 * 132;
#pragma unroll
        for (int ks = 0; ks < 128; ks += 8) {
            float af[4];
            af[0] = sv[ar0 + ks + tig];
            af[1] = sv[ar1 + ks + tig];
            af[2] = sv[ar0 + ks + 4 + tig];
            af[3] = sv[ar1 + ks + 4 + tig];
#pragma unroll
            for (int jt = 0; jt < 5; jt++) {
                float bf[2];
                bf[0] = Ws[(jt * 8 + gid) * 132 + ks + tig];
                bf[1] = Ws[(jt * 8 + gid) * 132 + ks + 4 + tig];
                mma8(racc[jt], af, bf);
            }
        }
    }
    __syncthreads();   // all reads of sv done; reuse as sS[128][40]

    // (e) scale by inverse norm, stage sS
    float* sS = sm;
    {
        int r1 = wid * 16 + gid, r2 = r1 + 8;
#pragma unroll
        for (int jt = 0; jt < 5; jt++) {
            int j0 = jt * 8 + tig * 2;
            int hh = (j0 >= LR);
            float n1 = snorm[r1 * 2 + hh], n2 = snorm[r2 * 2 + hh];
            sS[r1 * 40 + j0]     = tf32r(racc[jt][0] * n1);
            sS[r1 * 40 + j0 + 1] = tf32r(racc[jt][1] * n1);
            sS[r2 * 40 + j0]     = tf32r(racc[jt][2] * n2);
            sS[r2 * 40 + j0 + 1] = tf32r(racc[jt][3] * n2);
        }
    }
    __syncthreads();

    // (f) coalesced store to S
    for (int it = 0; it < 16; it++) {
        int r = wid + 8 * it;
        float* dst = S + ((size_t)(b * SEQ + nseq0 + r)) * KS2 + joff;
        if (lane < LR) {
            dst[(h0)     * 40 + lane] = sS[r * 40 + lane];
            dst[(h0 + 1) * 40 + lane] = sS[r * 40 + LR + lane];
        }
    }
}

// ---------------- generic tf32 GEMM (runtime K) ----------------
__global__ __launch_bounds__(256, 2) void gemm_tf32(
    const float* __restrict__ A, const float* __restrict__ B,
    const float* __restrict__ bias, float* __restrict__ C,
    int Nn, int K)
{
    extern __shared__ float sm[];
    const uint32_t sbase = smem_u32(sm);
    GEMM_PROLOG();
    const int m0 = blockIdx.y * 128, n0 = blockIdx.x * 128;

    GEMM_MAINLOOP(K, K / BK);

    float bb[4][2];
#pragma unroll
    for (int nt = 0; nt < 4; nt++) {
        int col = n0 + wn * 32 + nt * 8 + tig * 2;
        bb[nt][0] = bias[col];
        bb[nt][1] = bias[col + 1];
    }
#pragma unroll
    for (int mt = 0; mt < 4; mt++)
#pragma unroll
        for (int half = 0; half < 2; half++) {
            int row = m0 + wm * 64 + mt * 16 + gid + half * 8;
            float* cp = C + (size_t)row * Nn + n0 + wn * 32 + tig * 2;
#pragma unroll
            for (int nt = 0; nt < 4; nt++) {
                float2 v;
                v.x = acc[mt][nt][half * 2 + 0] + bb[nt][0];
                v.y = acc[mt][nt][half * 2 + 1] + bb[nt][1];
                *(float2*)(cp + nt * 8) = v;
            }
        }
}

// ---------------- launch ----------------
extern "C" void kernel_launch(void* const* d_in, const int* in_sizes, int n_in,
                              void* d_out, int out_size)
{
    const float* x      = (const float*)d_in[0];
    const float* qk_w   = (const float*)d_in[1];
    const float* proj_w = (const float*)d_in[2];
    const float* proj_b = (const float*)d_in[3];
    const float* we     = (const float*)d_in[4];
    const float* wr     = (const float*)d_in[5];
    const float* cw_w   = (const float*)d_in[6];
    const float* cw_b   = (const float*)d_in[7];
    float* out = (float*)d_out;

    float *xr, *qkwr, *webT, *wrbT, *S, *Bg, *ob;
    cudaGetSymbolAddress((void**)&xr,   g_xr);
    cudaGetSymbolAddress((void**)&qkwr, g_qkwr);
    cudaGetSymbolAddress((void**)&webT, g_webT);
    cudaGetSymbolAddress((void**)&wrbT, g_wrbT);
    cudaGetSymbolAddress((void**)&S,    g_S);
    cudaGetSymbolAddress((void**)&Bg,   g_Bg);
    cudaGetSymbolAddress((void**)&ob,   g_obias);

    const int gemm_smem = 3 * STAGE_FLT * 4;                  // 98304
    cudaFuncSetAttribute(gemm_qk,
                         cudaFuncAttributeMaxDynamicSharedMemorySize, gemm_smem);
    cudaFuncSetAttribute(gemm_tf32,
                         cudaFuncAttributeMaxDynamicSharedMemorySize, gemm_smem);
    const int prep_smem = PR_TOT * 4;                         // 83200
    cudaFuncSetAttribute(prep_kernel,
                         cudaFuncAttributeMaxDynamicSharedMemorySize, prep_smem);

    // tf32 rounding of x / qk_w  (occupancy-unbound streaming kernel)
    round_kernel<<<2048, 256>>>(x, qk_w, xr, qkwr);
    // gen_weights + Bg/obias (128 smem-heavy blocks)
    prep_kernel<<<NBH + 64, 256, prep_smem>>>(
        x, we, wr, proj_w, cw_w, proj_b, cw_b, webT, wrbT, Bg, ob);

    // 1) qk gemm fused with normalize + tensor-core score epilogue -> S
    {
        dim3 grid(QKW / 128, MTOT / 128);
        gemm_qk<<<grid, 256, gemm_smem>>>(xr, qkwr, webT, wrbT, S);
    }
    // 2) out = S @ Bg^T + obias   (M=8192, Nn=1024, K=640)
    {
        dim3 grid(CH / 128, MTOT / 128);
        gemm_tf32<<<grid, 256, gemm_smem>>>(S, Bg, ob, out, CH, KS2);
    }
}